// round 1
// baseline (speedup 1.0000x reference)
#include <cuda_runtime.h>
#include <math.h>

#define DIMC 512
#define NTOK 8192      // B*N
#define SEQ  4096
#define BATCH 2
#define HEADS 8
#define HD   64
#define C3   1536
#define MLPH 2048

// ---- scratch (static __device__ globals; no allocation) ----
__device__ float g_h  [(size_t)NTOK*DIMC];             // ln1 out / pe hidden / ln2 out
__device__ float g_pe [(size_t)NTOK*DIMC];
__device__ float g_qkv[(size_t)NTOK*C3];
__device__ float g_S  [(size_t)BATCH*HEADS*SEQ*SEQ];   // 1 GiB attention scores
__device__ float g_o  [(size_t)NTOK*DIMC];
__device__ float g_x2 [(size_t)NTOK*DIMC];
__device__ float g_m1 [(size_t)NTOK*MLPH];

__device__ __forceinline__ float gelu_f(float v){
    return 0.5f * v * (1.0f + erff(v * 0.70710678118654752440f));
}

// ---------------- LayerNorm: one block (256 thr) per row of 512 ----------------
__global__ void ln_kernel(const float* __restrict__ x, const float* __restrict__ g,
                          const float* __restrict__ beta, float* __restrict__ y){
    long long row = blockIdx.x;
    const float* xr = x + row * DIMC;
    int t = threadIdx.x;
    float a0 = xr[t], a1 = xr[t + 256];
    float s  = a0 + a1;
    float ss = a0*a0 + a1*a1;
    #pragma unroll
    for (int o = 16; o > 0; o >>= 1){
        s  += __shfl_xor_sync(0xffffffffu, s,  o);
        ss += __shfl_xor_sync(0xffffffffu, ss, o);
    }
    __shared__ float s1[8], s2[8];
    if ((t & 31) == 0){ s1[t >> 5] = s; s2[t >> 5] = ss; }
    __syncthreads();
    float tot = 0.f, tot2 = 0.f;
    #pragma unroll
    for (int i = 0; i < 8; i++){ tot += s1[i]; tot2 += s2[i]; }
    float mu  = tot * (1.0f / DIMC);
    float var = tot2 * (1.0f / DIMC) - mu * mu;
    float rs  = rsqrtf(var + 1e-5f);
    float* yr = y + row * DIMC;
    yr[t]       = (a0 - mu) * rs * g[t]       + beta[t];
    yr[t + 256] = (a1 - mu) * rs * g[t + 256] + beta[t + 256];
}

// ---------------- generic tiled SGEMM: 64x64x16, 256 threads, 4x4 micro ----------------
// C[z] = alpha * A[z] @ op(B[z]) (+bias) (gelu) (+res).  op = B^T when TB.
// batch index z -> (b = z/HZ, h = z%HZ); per-operand (b,h) strides.
template<bool TB>
__global__ void __launch_bounds__(256) sgemm_kernel(
    const float* __restrict__ A, const float* __restrict__ B,
    const float* __restrict__ bias, const float* __restrict__ res,
    float* __restrict__ C,
    int K, int lda, int ldb, int ldc,
    long long sAb, long long sAh, long long sBb, long long sBh,
    long long sCb, long long sCh, int HZ,
    float alpha, int epi)   // epi: 0 none, 1 gelu, 2 residual
{
    int bz = blockIdx.z;
    int bb = bz / HZ, hh = bz % HZ;
    A += (long long)bb * sAb + (long long)hh * sAh;
    B += (long long)bb * sBb + (long long)hh * sBh;
    C += (long long)bb * sCb + (long long)hh * sCh;
    if (res) res += (long long)bb * sCb + (long long)hh * sCh;

    __shared__ float As[16][64];
    __shared__ float Bs[16][64];

    int tx = threadIdx.x, ty = threadIdx.y;
    int tid = ty * 16 + tx;
    int aRow = tid >> 2,  aCol = (tid & 3)  << 2;   // A tile 64x16
    int bRow = tid >> 4,  bCol = (tid & 15) << 2;   // B tile 16x64 (no-trans)
    int bN   = tid >> 2,  bK   = (tid & 3)  << 2;   // B tile (trans)

    const float* Ab = A + (long long)(blockIdx.y * 64 + aRow) * lda + aCol;

    float acc[4][4];
    #pragma unroll
    for (int i = 0; i < 4; i++)
        #pragma unroll
        for (int j = 0; j < 4; j++) acc[i][j] = 0.f;

    for (int k0 = 0; k0 < K; k0 += 16){
        float4 av = *(const float4*)(Ab + k0);
        As[aCol + 0][aRow] = av.x; As[aCol + 1][aRow] = av.y;
        As[aCol + 2][aRow] = av.z; As[aCol + 3][aRow] = av.w;
        if (!TB){
            float4 bv = *(const float4*)(B + (long long)(k0 + bRow) * ldb
                                           + blockIdx.x * 64 + bCol);
            *(float4*)&Bs[bRow][bCol] = bv;
        } else {
            float4 bv = *(const float4*)(B + (long long)(blockIdx.x * 64 + bN) * ldb
                                           + k0 + bK);
            Bs[bK + 0][bN] = bv.x; Bs[bK + 1][bN] = bv.y;
            Bs[bK + 2][bN] = bv.z; Bs[bK + 3][bN] = bv.w;
        }
        __syncthreads();
        #pragma unroll
        for (int kk = 0; kk < 16; kk++){
            float4 a = *(const float4*)&As[kk][ty << 2];
            float4 b = *(const float4*)&Bs[kk][tx << 2];
            float ar[4] = {a.x, a.y, a.z, a.w};
            float br[4] = {b.x, b.y, b.z, b.w};
            #pragma unroll
            for (int i = 0; i < 4; i++)
                #pragma unroll
                for (int j = 0; j < 4; j++)
                    acc[i][j] += ar[i] * br[j];
        }
        __syncthreads();
    }

    int col0 = blockIdx.x * 64 + (tx << 2);
    #pragma unroll
    for (int i = 0; i < 4; i++){
        long long r = (long long)(blockIdx.y * 64 + (ty << 2) + i);
        float4 v;
        float* pv = &v.x;
        #pragma unroll
        for (int j = 0; j < 4; j++){
            float t = acc[i][j] * alpha;
            if (bias)     t += bias[col0 + j];
            if (epi == 1) t  = gelu_f(t);
            if (epi == 2) t += res[r * ldc + col0 + j];
            pv[j] = t;
        }
        *(float4*)(C + r * ldc + col0) = v;
    }
}

// ---------------- PE layer 1: t = gelu(pos @ W1 + b1), K=3 ----------------
__global__ void pe1_kernel(const float* __restrict__ pos, const float* __restrict__ w1,
                           const float* __restrict__ b1, float* __restrict__ t_out){
    int idx = blockIdx.x * 256 + threadIdx.x;   // 8192*512
    int m = idx >> 9, c = idx & 511;
    float p0 = pos[m * 3], p1 = pos[m * 3 + 1], p2 = pos[m * 3 + 2];
    float v = p0 * w1[c] + p1 * w1[512 + c] + p2 * w1[1024 + c] + b1[c];
    t_out[idx] = gelu_f(v);
}

// ---------------- add PE into Q and K slabs of qkv ----------------
__global__ void addpe_kernel(float* __restrict__ qkv, const float* __restrict__ pe){
    int idx = blockIdx.x * 256 + threadIdx.x;   // 8192*512
    int m = idx >> 9, c = idx & 511;
    float v = pe[idx];
    long long base = (long long)m * C3 + c;
    qkv[base]       += v;   // q
    qkv[base + 512] += v;   // k
}

// ---------------- softmax: one block (256 thr) per row of 4096, values in regs ----------------
__global__ void softmax_kernel(float* __restrict__ S){
    float* p = S + (long long)blockIdx.x * SEQ;
    int t = threadIdx.x;
    float v[16];
    float mx = -3.4e38f;
    #pragma unroll
    for (int i = 0; i < 16; i++){ v[i] = p[i * 256 + t]; mx = fmaxf(mx, v[i]); }
    #pragma unroll
    for (int o = 16; o > 0; o >>= 1) mx = fmaxf(mx, __shfl_xor_sync(0xffffffffu, mx, o));
    __shared__ float sm[8];
    if ((t & 31) == 0) sm[t >> 5] = mx;
    __syncthreads();
    #pragma unroll
    for (int i = 0; i < 8; i++) mx = fmaxf(mx, sm[i]);
    float s = 0.f;
    #pragma unroll
    for (int i = 0; i < 16; i++){ v[i] = expf(v[i] - mx); s += v[i]; }
    #pragma unroll
    for (int o = 16; o > 0; o >>= 1) s += __shfl_xor_sync(0xffffffffu, s, o);
    __shared__ float ss[8];
    if ((t & 31) == 0) ss[t >> 5] = s;
    __syncthreads();
    float tot = 0.f;
    #pragma unroll
    for (int i = 0; i < 8; i++) tot += ss[i];
    float inv = 1.0f / tot;
    #pragma unroll
    for (int i = 0; i < 16; i++) p[i * 256 + t] = v[i] * inv;
}

extern "C" void kernel_launch(void* const* d_in, const int* in_sizes, int n_in,
                              void* d_out, int out_size){
    const float* x      = (const float*)d_in[0];
    const float* pos    = (const float*)d_in[1];
    const float* qkv_w  = (const float*)d_in[2];
    const float* qkv_b  = (const float*)d_in[3];
    const float* proj_w = (const float*)d_in[4];
    const float* proj_b = (const float*)d_in[5];
    const float* pe_w1  = (const float*)d_in[6];
    const float* pe_b1  = (const float*)d_in[7];
    const float* pe_w2  = (const float*)d_in[8];
    const float* pe_b2  = (const float*)d_in[9];
    const float* mlp_w1 = (const float*)d_in[10];
    const float* mlp_b1 = (const float*)d_in[11];
    const float* mlp_w2 = (const float*)d_in[12];
    const float* mlp_b2 = (const float*)d_in[13];
    const float* n1_g   = (const float*)d_in[14];
    const float* n1_b   = (const float*)d_in[15];
    const float* n2_g   = (const float*)d_in[16];
    const float* n2_b   = (const float*)d_in[17];
    float* out = (float*)d_out;

    float *h, *pe, *qkv, *S, *o, *x2, *m1;
    cudaGetSymbolAddress((void**)&h,   g_h);
    cudaGetSymbolAddress((void**)&pe,  g_pe);
    cudaGetSymbolAddress((void**)&qkv, g_qkv);
    cudaGetSymbolAddress((void**)&S,   g_S);
    cudaGetSymbolAddress((void**)&o,   g_o);
    cudaGetSymbolAddress((void**)&x2,  g_x2);
    cudaGetSymbolAddress((void**)&m1,  g_m1);

    dim3 tb(16, 16);
    const long long sSh = (long long)SEQ * SEQ;          // head stride in S
    const long long sSb = (long long)HEADS * sSh;        // batch stride in S
    const long long sQb = (long long)SEQ * C3;           // batch stride in qkv rows
    const long long sOb = (long long)SEQ * DIMC;

    // 1. h = LN1(x)
    ln_kernel<<<NTOK, 256>>>(x, n1_g, n1_b, h);

    // 2. qkv = h @ qkv_w + qkv_b   [8192,1536]
    sgemm_kernel<false><<<dim3(C3/64, NTOK/64, 1), tb>>>(
        h, qkv_w, qkv_b, nullptr, qkv,
        DIMC, DIMC, C3, C3, 0,0,0,0,0,0, 1, 1.0f, 0);

    // 3. pe hidden = gelu(pos @ pe_w1 + pe_b1)  (reuse h)
    pe1_kernel<<<(NTOK*DIMC)/256, 256>>>(pos, pe_w1, pe_b1, h);

    // 4. pe = hidden @ pe_w2 + pe_b2
    sgemm_kernel<false><<<dim3(DIMC/64, NTOK/64, 1), tb>>>(
        h, pe_w2, pe_b2, nullptr, pe,
        DIMC, DIMC, DIMC, DIMC, 0,0,0,0,0,0, 1, 1.0f, 0);

    // 5. q += pe, k += pe
    addpe_kernel<<<(NTOK*DIMC)/256, 256>>>(qkv, pe);

    // 6. S = (q @ k^T) * scale   per (b,h):  M=N=4096, K=64
    sgemm_kernel<true><<<dim3(SEQ/64, SEQ/64, BATCH*HEADS), tb>>>(
        qkv, qkv + 512, nullptr, nullptr, S,
        HD, C3, C3, SEQ,
        sQb, 64, sQb, 64, sSb, sSh, HEADS, 0.125f, 0);

    // 7. softmax rows
    softmax_kernel<<<BATCH*HEADS*SEQ, 256>>>(S);

    // 8. o = P @ V   per (b,h):  M=4096, N=64, K=4096
    sgemm_kernel<false><<<dim3(HD/64, SEQ/64, BATCH*HEADS), tb>>>(
        S, qkv + 1024, nullptr, nullptr, o,
        SEQ, SEQ, C3, DIMC,
        sSb, sSh, sQb, 64, sOb, 64, HEADS, 1.0f, 0);

    // 9. x2 = x + o @ proj_w + proj_b
    sgemm_kernel<false><<<dim3(DIMC/64, NTOK/64, 1), tb>>>(
        o, proj_w, proj_b, x, x2,
        DIMC, DIMC, DIMC, DIMC, 0,0,0,0,0,0, 1, 1.0f, 2);

    // 10. h = LN2(x2)
    ln_kernel<<<NTOK, 256>>>(x2, n2_g, n2_b, h);

    // 11. m1 = gelu(h @ mlp_w1 + mlp_b1)
    sgemm_kernel<false><<<dim3(MLPH/64, NTOK/64, 1), tb>>>(
        h, mlp_w1, mlp_b1, nullptr, m1,
        DIMC, DIMC, MLPH, MLPH, 0,0,0,0,0,0, 1, 1.0f, 1);

    // 12. out = x2 + m1 @ mlp_w2 + mlp_b2
    sgemm_kernel<false><<<dim3(DIMC/64, NTOK/64, 1), tb>>>(
        m1, mlp_w2, mlp_b2, x2, out,
        MLPH, MLPH, DIMC, DIMC, 0,0,0,0,0,0, 1, 1.0f, 2);
}

// round 5
// speedup vs baseline: 2.5400x; 2.5400x over previous
#include <cuda_runtime.h>
#include <cuda_bf16.h>
#include <math.h>
#include <stdint.h>

#define DIMC 512
#define NTOK 8192      // B*N
#define SEQ  4096
#define BATCH 2
#define HEADS 8
#define HD   64
#define C3   1536
#define MLPH 2048
#define BH   16        // BATCH*HEADS

// ============================ scratch buffers (~450 MB total) ============================
__device__ __align__(256) __nv_bfloat16 g_hA  [8192ULL*1536];   // ln out split A (hi|lo|hi)
__device__ __align__(256) float         g_qkvf[8192ULL*1536];
__device__ __align__(256) float         g_pef [8192ULL*512];
__device__ __align__(256) __nv_bfloat16 g_qA  [16ULL*4096*192]; // q split (hi|lo|hi), scale folded
__device__ __align__(256) __nv_bfloat16 g_kB  [16ULL*4096*192]; // k split (hi|hi|lo)
__device__ __align__(256) __nv_bfloat16 g_vBh [16ULL*64*4096];  // V_hi transposed [bh][d][n]
__device__ __align__(256) __nv_bfloat16 g_vBl [16ULL*64*4096];  // V_lo transposed
__device__ __align__(256) float         g_of  [8192ULL*512];
__device__ __align__(256) __nv_bfloat16 g_oA  [8192ULL*1536];
__device__ __align__(256) float         g_x2f [8192ULL*512];
__device__ __align__(256) float         g_m1f [8192ULL*2048];
__device__ __align__(256) __nv_bfloat16 g_m1A [8192ULL*6144];   // also hosts peA (disjoint lifetime)
__device__ __align__(256) __nv_bfloat16 g_qkvB [1536ULL*1536];  // weights (hi|hi|lo), transposed
__device__ __align__(256) __nv_bfloat16 g_pe2B [512ULL*1536];
__device__ __align__(256) __nv_bfloat16 g_projB[512ULL*1536];
__device__ __align__(256) __nv_bfloat16 g_mlp1B[2048ULL*1536];
__device__ __align__(256) __nv_bfloat16 g_mlp2B[512ULL*6144];

// ============================ helpers ============================
__device__ __forceinline__ uint32_t smem_u32(const void* p){
    uint32_t a;
    asm("{ .reg .u64 t; cvta.to.shared.u64 t, %1; cvt.u32.u64 %0, t; }" : "=r"(a) : "l"(p));
    return a;
}
__device__ __forceinline__ float gelu_f(float v){
    return 0.5f * v * (1.0f + erff(v * 0.70710678118654752440f));
}
__device__ __forceinline__ void split2(float x, __nv_bfloat16& hi, __nv_bfloat16& lo){
    hi = __float2bfloat16(x);
    lo = __float2bfloat16(x - __bfloat162float(hi));
}
__device__ __forceinline__ uint32_t packbf(float f0, float f1){
    __nv_bfloat162 t;
    t.x = __float2bfloat16(f0);
    t.y = __float2bfloat16(f1);
    return *(uint32_t*)&t;
}
__device__ __forceinline__ void cpasync16(uint32_t dst, const void* src, bool pred){
    asm volatile("cp.async.cg.shared.global [%0], [%1], 16, %2;"
                 :: "r"(dst), "l"(src), "r"(pred ? 16 : 0) : "memory");
}
#define CP_COMMIT()  asm volatile("cp.async.commit_group;" ::: "memory")
#define CP_WAIT(n)   asm volatile("cp.async.wait_group %0;" :: "n"(n) : "memory")

__device__ __forceinline__ void ldm_x4(uint32_t addr, uint32_t& r0, uint32_t& r1,
                                       uint32_t& r2, uint32_t& r3){
    asm volatile("ldmatrix.sync.aligned.m8n8.x4.shared.b16 {%0,%1,%2,%3}, [%4];"
                 : "=r"(r0), "=r"(r1), "=r"(r2), "=r"(r3) : "r"(addr));
}
__device__ __forceinline__ void mma16816(float* c, const uint32_t* a, const uint32_t* b){
    asm volatile("mma.sync.aligned.m16n8k16.row.col.f32.bf16.bf16.f32 "
                 "{%0,%1,%2,%3}, {%4,%5,%6,%7}, {%8,%9}, {%0,%1,%2,%3};"
                 : "+f"(c[0]), "+f"(c[1]), "+f"(c[2]), "+f"(c[3])
                 : "r"(a[0]), "r"(a[1]), "r"(a[2]), "r"(a[3]), "r"(b[0]), "r"(b[1]));
}

// ============================ mma.sync GEMM ============================
// C[M,Ntot] = alpha * A[M,Kp] @ B[Ntot,Kp]^T (+bias)(gelu)(+res).
// 128x128 tile, BK=64, 8 warps (4m x 2n), cp.async double buffer.
#define ROWB 144                 // smem row stride bytes (64 bf16 + 8 pad)
#define TBUF (128 * ROWB)        // 18432 bytes per tile buffer
#define DYN_SMEM (4 * TBUF)      // 73728

__device__ __forceinline__ void load_tile(const __nv_bfloat16* __restrict__ G, int ldE,
                                          int nrows, uint32_t smbase, int tid){
    #pragma unroll
    for (int i = 0; i < 4; i++){
        int id  = tid + i * 256;          // 0..1023
        int r   = id >> 3, c16 = id & 7;
        bool p  = r < nrows;
        const char* src = (const char*)(G + (long long)(p ? r : 0) * ldE) + c16 * 16;
        cpasync16(smbase + r * ROWB + c16 * 16, src, p);
    }
}

__global__ void __launch_bounds__(256, 1) mmagemm(
    const __nv_bfloat16* __restrict__ A, const __nv_bfloat16* __restrict__ B,
    const float* __restrict__ bias, const float* __restrict__ res,
    float* __restrict__ C,
    int Kp, int lda, int ldb, int ldc, int Ntot,
    long long sAz, long long sBz, long long sCb, long long sCh, int HZ,
    float alpha, int epi)
{
    extern __shared__ char dynsm[];
    int tid = threadIdx.x, lane = tid & 31, w = tid >> 5;
    int wm = (w & 3) * 32, wn = (w >> 2) * 64;

    int z = blockIdx.z;
    int bb = z / HZ, hh = z % HZ;
    A += (long long)z * sAz;
    B += (long long)z * sBz;
    long long coff = (long long)bb * sCb + (long long)hh * sCh;

    int m0 = blockIdx.y * 128;
    int n0 = blockIdx.x * 128;
    int NT = Ntot - n0; if (NT > 128) NT = 128;

    uint32_t smu = smem_u32(dynsm);
    uint32_t asb[2] = { smu,            smu + 2 * TBUF };
    uint32_t bsb[2] = { smu + TBUF,     smu + 3 * TBUF };

    float acc[2][8][4];
    #pragma unroll
    for (int i = 0; i < 2; i++)
        #pragma unroll
        for (int j = 0; j < 8; j++)
            #pragma unroll
            for (int q = 0; q < 4; q++) acc[i][j][q] = 0.f;

    int nc = Kp >> 6;
    load_tile(A + (long long)m0 * lda, lda, 128, asb[0], tid);
    load_tile(B + (long long)n0 * ldb, ldb, NT,  bsb[0], tid);
    CP_COMMIT();

    for (int c = 0; c < nc; c++){
        int cur = c & 1;
        if (c + 1 < nc){
            load_tile(A + (long long)m0 * lda + (c + 1) * 64, lda, 128, asb[cur ^ 1], tid);
            load_tile(B + (long long)n0 * ldb + (c + 1) * 64, ldb, NT,  bsb[cur ^ 1], tid);
            CP_COMMIT();
            CP_WAIT(1);
        } else {
            CP_WAIT(0);
        }
        __syncthreads();

        #pragma unroll
        for (int kk = 0; kk < 4; kk++){
            uint32_t afr[2][4], bfr[4][4];
            #pragma unroll
            for (int mt = 0; mt < 2; mt++){
                int row = wm + mt * 16 + (lane & 15);
                uint32_t addr = asb[cur] + row * ROWB + kk * 32 + ((lane >> 4) << 4);
                ldm_x4(addr, afr[mt][0], afr[mt][1], afr[mt][2], afr[mt][3]);
            }
            #pragma unroll
            for (int np = 0; np < 4; np++){
                int row = wn + np * 16 + ((lane & 7) | ((lane >> 4) << 3));
                uint32_t addr = bsb[cur] + row * ROWB + kk * 32 + (((lane >> 3) & 1) << 4);
                ldm_x4(addr, bfr[np][0], bfr[np][1], bfr[np][2], bfr[np][3]);
            }
            #pragma unroll
            for (int mt = 0; mt < 2; mt++)
                #pragma unroll
                for (int nt = 0; nt < 8; nt++)
                    mma16816(acc[mt][nt], afr[mt], &bfr[nt >> 1][(nt & 1) * 2]);
        }
        __syncthreads();
    }

    // epilogue: regs -> smem stage -> coalesced global
    float* Cs = (float*)dynsm;   // 128 x 132 floats
    #pragma unroll
    for (int mt = 0; mt < 2; mt++)
        #pragma unroll
        for (int nt = 0; nt < 8; nt++){
            int r  = wm + mt * 16 + (lane >> 2);
            int cc = wn + nt * 8 + (lane & 3) * 2;
            Cs[r * 132 + cc]           = acc[mt][nt][0];
            Cs[r * 132 + cc + 1]       = acc[mt][nt][1];
            Cs[(r + 8) * 132 + cc]     = acc[mt][nt][2];
            Cs[(r + 8) * 132 + cc + 1] = acc[mt][nt][3];
        }
    __syncthreads();

    for (int e = tid; e < 128 * 128; e += 256){
        int rr = e >> 7, cc = e & 127;
        int gc = n0 + cc;
        if (gc < Ntot){
            float v = Cs[rr * 132 + cc] * alpha;
            if (bias)     v += bias[gc];
            if (epi & 1)  v  = gelu_f(v);
            long long ga = coff + (long long)(m0 + rr) * ldc + gc;
            if (epi & 2)  v += res[ga];
            C[ga] = v;
        }
    }
}

// ============================ flash attention ============================
// Per CTA: 128 q rows of one (b,h). K'=192 (split), 64-key chunks, online softmax.
// Q in registers; K and V^T(hi/lo) double-buffered in smem.
#define QROWB 400
#define KROWB 400
#define VROWB 144
#define FA_QS   0
#define FA_KS   51200                       // + buf*25600
#define FA_VH   (51200 + 2*25600)           // + buf*9216
#define FA_VL   (FA_VH + 2*9216)
#define FA_SMEM (FA_VL + 2*9216)            // 139264

__device__ __forceinline__ void fa_load_kv(
    const __nv_bfloat16* __restrict__ kB, const __nv_bfloat16* __restrict__ vh,
    const __nv_bfloat16* __restrict__ vl,
    long long kbase, long long vbase, int c, uint32_t smu, int buf, int tid)
{
    uint32_t ks  = smu + FA_KS + buf * 25600;
    uint32_t vhs = smu + FA_VH + buf * 9216;
    uint32_t vls = smu + FA_VL + buf * 9216;
    #pragma unroll
    for (int i = 0; i < 6; i++){            // K: 64 rows x 384B
        int id = tid + i * 256;
        int r = id / 24, c16 = id % 24;
        cpasync16(ks + r * KROWB + c16 * 16,
                  kB + kbase + (long long)(c * 64 + r) * 192 + c16 * 8, true);
    }
    #pragma unroll
    for (int i = 0; i < 2; i++){            // V^T hi/lo: 64 rows x 128B each
        int id = tid + i * 256;
        int r = id >> 3, c16 = id & 7;
        cpasync16(vhs + r * VROWB + c16 * 16,
                  vh + vbase + (long long)r * 4096 + c * 64 + c16 * 8, true);
        cpasync16(vls + r * VROWB + c16 * 16,
                  vl + vbase + (long long)r * 4096 + c * 64 + c16 * 8, true);
    }
}

__global__ void __launch_bounds__(256, 1) flash_attn(
    const __nv_bfloat16* __restrict__ qA, const __nv_bfloat16* __restrict__ kB,
    const __nv_bfloat16* __restrict__ vh, const __nv_bfloat16* __restrict__ vl,
    float* __restrict__ of)
{
    extern __shared__ char dynsm[];
    uint32_t smu = smem_u32(dynsm);
    int tid = threadIdx.x, lane = tid & 31, w = tid >> 5;
    int bh = blockIdx.y;
    int b = bh >> 3, h = bh & 7;
    int m0 = blockIdx.x * 128;

    long long qbase = ((long long)bh * 4096 + m0) * 192;
    long long kbase = (long long)bh * 4096 * 192;
    long long vbase = (long long)bh * 64 * 4096;

    // ---- load Q tile (group 0) ----
    #pragma unroll
    for (int i = 0; i < 12; i++){           // 128 rows x 384B
        int id = tid + i * 256;
        int r = id / 24, c16 = id % 24;
        cpasync16(smu + FA_QS + r * QROWB + c16 * 16,
                  qA + qbase + (long long)r * 192 + c16 * 8, true);
    }
    CP_COMMIT();
    // ---- prefetch KV chunk 0 (group 1) ----
    fa_load_kv(kB, vh, vl, kbase, vbase, 0, smu, 0, tid);
    CP_COMMIT();
    CP_WAIT(1);                             // Q ready
    __syncthreads();

    // ---- Q fragments into registers ----
    uint32_t qf[12][4];
    #pragma unroll
    for (int kk = 0; kk < 12; kk++){
        int row = w * 16 + (lane & 15);
        uint32_t addr = smu + FA_QS + row * QROWB + kk * 32 + ((lane >> 4) << 4);
        ldm_x4(addr, qf[kk][0], qf[kk][1], qf[kk][2], qf[kk][3]);
    }

    float O[8][4];
    #pragma unroll
    for (int i = 0; i < 8; i++)
        #pragma unroll
        for (int j = 0; j < 4; j++) O[i][j] = 0.f;
    float m0s = -1e30f, m1s = -1e30f, l0 = 0.f, l1 = 0.f;

    for (int c = 0; c < 64; c++){
        int buf = c & 1;
        if (c + 1 < 64){
            fa_load_kv(kB, vh, vl, kbase, vbase, c + 1, smu, buf ^ 1, tid);
            CP_COMMIT();
            CP_WAIT(1);
        } else {
            CP_WAIT(0);
        }
        __syncthreads();

        uint32_t ks  = smu + FA_KS + buf * 25600;
        uint32_t vhs = smu + FA_VH + buf * 9216;
        uint32_t vls = smu + FA_VL + buf * 9216;

        // ---- S = Q @ K^T ----
        float S[8][4];
        #pragma unroll
        for (int i = 0; i < 8; i++)
            #pragma unroll
            for (int j = 0; j < 4; j++) S[i][j] = 0.f;
        #pragma unroll
        for (int kk = 0; kk < 12; kk++){
            uint32_t bfr[4][4];
            #pragma unroll
            for (int np = 0; np < 4; np++){
                int row = np * 16 + ((lane & 7) | ((lane >> 4) << 3));
                uint32_t addr = ks + row * KROWB + kk * 32 + (((lane >> 3) & 1) << 4);
                ldm_x4(addr, bfr[np][0], bfr[np][1], bfr[np][2], bfr[np][3]);
            }
            #pragma unroll
            for (int nt = 0; nt < 8; nt++)
                mma16816(S[nt], qf[kk], &bfr[nt >> 1][(nt & 1) * 2]);
        }

        // ---- online softmax ----
        float mx0 = -1e30f, mx1 = -1e30f;
        #pragma unroll
        for (int nt = 0; nt < 8; nt++){
            mx0 = fmaxf(mx0, fmaxf(S[nt][0], S[nt][1]));
            mx1 = fmaxf(mx1, fmaxf(S[nt][2], S[nt][3]));
        }
        mx0 = fmaxf(mx0, __shfl_xor_sync(0xffffffffu, mx0, 1));
        mx0 = fmaxf(mx0, __shfl_xor_sync(0xffffffffu, mx0, 2));
        mx1 = fmaxf(mx1, __shfl_xor_sync(0xffffffffu, mx1, 1));
        mx1 = fmaxf(mx1, __shfl_xor_sync(0xffffffffu, mx1, 2));
        float nm0 = fmaxf(m0s, mx0), nm1 = fmaxf(m1s, mx1);
        float sc0 = __expf(m0s - nm0), sc1 = __expf(m1s - nm1);
        float sum0 = 0.f, sum1 = 0.f;
        #pragma unroll
        for (int nt = 0; nt < 8; nt++){
            S[nt][0] = __expf(S[nt][0] - nm0); sum0 += S[nt][0];
            S[nt][1] = __expf(S[nt][1] - nm0); sum0 += S[nt][1];
            S[nt][2] = __expf(S[nt][2] - nm1); sum1 += S[nt][2];
            S[nt][3] = __expf(S[nt][3] - nm1); sum1 += S[nt][3];
        }
        sum0 += __shfl_xor_sync(0xffffffffu, sum0, 1);
        sum0 += __shfl_xor_sync(0xffffffffu, sum0, 2);
        sum1 += __shfl_xor_sync(0xffffffffu, sum1, 1);
        sum1 += __shfl_xor_sync(0xffffffffu, sum1, 2);
        l0 = l0 * sc0 + sum0; l1 = l1 * sc1 + sum1;
        m0s = nm0; m1s = nm1;
        #pragma unroll
        for (int nt = 0; nt < 8; nt++){
            O[nt][0] *= sc0; O[nt][1] *= sc0;
            O[nt][2] *= sc1; O[nt][3] *= sc1;
        }

        // ---- O += P @ V (3-term split) ----
        #pragma unroll
        for (int kc = 0; kc < 4; kc++){
            uint32_t ph[4], pl[4];
            {
                int ta = 2 * kc, tb = 2 * kc + 1;
                ph[0] = packbf(S[ta][0], S[ta][1]);
                ph[1] = packbf(S[ta][2], S[ta][3]);
                ph[2] = packbf(S[tb][0], S[tb][1]);
                ph[3] = packbf(S[tb][2], S[tb][3]);
                __nv_bfloat162* hp;
                hp = (__nv_bfloat162*)&ph[0];
                pl[0] = packbf(S[ta][0] - __bfloat162float(hp->x), S[ta][1] - __bfloat162float(hp->y));
                hp = (__nv_bfloat162*)&ph[1];
                pl[1] = packbf(S[ta][2] - __bfloat162float(hp->x), S[ta][3] - __bfloat162float(hp->y));
                hp = (__nv_bfloat162*)&ph[2];
                pl[2] = packbf(S[tb][0] - __bfloat162float(hp->x), S[tb][1] - __bfloat162float(hp->y));
                hp = (__nv_bfloat162*)&ph[3];
                pl[3] = packbf(S[tb][2] - __bfloat162float(hp->x), S[tb][3] - __bfloat162float(hp->y));
            }
            uint32_t vhf[4][4], vlf[4][4];
            #pragma unroll
            for (int np = 0; np < 4; np++){
                int row = np * 16 + ((lane & 7) | ((lane >> 4) << 3));
                uint32_t col = kc * 32 + (((lane >> 3) & 1) << 4);
                ldm_x4(vhs + row * VROWB + col, vhf[np][0], vhf[np][1], vhf[np][2], vhf[np][3]);
                ldm_x4(vls + row * VROWB + col, vlf[np][0], vlf[np][1], vlf[np][2], vlf[np][3]);
            }
            #pragma unroll
            for (int nt = 0; nt < 8; nt++){
                mma16816(O[nt], ph, &vhf[nt >> 1][(nt & 1) * 2]);
                mma16816(O[nt], pl, &vhf[nt >> 1][(nt & 1) * 2]);
                mma16816(O[nt], ph, &vlf[nt >> 1][(nt & 1) * 2]);
            }
        }
        __syncthreads();
    }

    // ---- write O / l ----
    float inv0 = 1.0f / l0, inv1 = 1.0f / l1;
    int r0 = w * 16 + (lane >> 2);
    int col = (lane & 3) * 2;
    long long tok0 = (long long)b * 4096 + m0 + r0;
    #pragma unroll
    for (int nt = 0; nt < 8; nt++){
        int d = nt * 8 + col;
        float2 v0 = make_float2(O[nt][0] * inv0, O[nt][1] * inv0);
        float2 v1 = make_float2(O[nt][2] * inv1, O[nt][3] * inv1);
        *(float2*)(of + tok0 * 512 + h * 64 + d)       = v0;
        *(float2*)(of + (tok0 + 8) * 512 + h * 64 + d) = v1;
    }
}

// ============================ LayerNorm -> split A ============================
__global__ void ln_split(const float* __restrict__ x, const float* __restrict__ g,
                         const float* __restrict__ beta, __nv_bfloat16* __restrict__ y){
    long long row = blockIdx.x;
    const float* xr = x + row * DIMC;
    int t = threadIdx.x;
    float a0 = xr[t], a1 = xr[t + 256];
    float s  = a0 + a1, ss = a0 * a0 + a1 * a1;
    #pragma unroll
    for (int o = 16; o > 0; o >>= 1){
        s  += __shfl_xor_sync(0xffffffffu, s,  o);
        ss += __shfl_xor_sync(0xffffffffu, ss, o);
    }
    __shared__ float s1[8], s2[8];
    if ((t & 31) == 0){ s1[t >> 5] = s; s2[t >> 5] = ss; }
    __syncthreads();
    float tot = 0.f, tot2 = 0.f;
    #pragma unroll
    for (int i = 0; i < 8; i++){ tot += s1[i]; tot2 += s2[i]; }
    float mu  = tot * (1.0f / DIMC);
    float var = tot2 * (1.0f / DIMC) - mu * mu;
    float rsv = rsqrtf(var + 1e-5f);
    __nv_bfloat16* yr = y + row * (3 * DIMC);
    float y0 = (a0 - mu) * rsv * g[t] + beta[t];
    float y1 = (a1 - mu) * rsv * g[t + 256] + beta[t + 256];
    __nv_bfloat16 h0, l0, h1, l1;
    split2(y0, h0, l0); split2(y1, h1, l1);
    yr[t] = h0;  yr[512 + t] = l0;  yr[1024 + t] = h0;
    yr[t + 256] = h1; yr[512 + t + 256] = l1; yr[1024 + t + 256] = h1;
}

// ============================ elementwise split (A pattern hi|lo|hi) ============================
__global__ void splitA(const float* __restrict__ in, __nv_bfloat16* __restrict__ out, int K){
    long long idx = (long long)blockIdx.x * 256 + threadIdx.x;
    long long m = idx / K; int k = (int)(idx % K);
    float v = in[idx];
    __nv_bfloat16 hi, lo; split2(v, hi, lo);
    __nv_bfloat16* o = out + m * (3LL * K);
    o[k] = hi; o[K + k] = lo; o[2 * K + k] = hi;
}

// ============================ weight transpose-split (B pattern hi|hi|lo) ============================
__global__ void tsplit(const float* __restrict__ W, __nv_bfloat16* __restrict__ out, int K, int N){
    __shared__ float tile[32][33];
    int k0 = blockIdx.x * 32, n0 = blockIdx.y * 32;
    int tx = threadIdx.x, ty = threadIdx.y;
    #pragma unroll
    for (int j = 0; j < 4; j++)
        tile[ty + j * 8][tx] = W[(long long)(k0 + ty + j * 8) * N + n0 + tx];
    __syncthreads();
    #pragma unroll
    for (int j = 0; j < 4; j++){
        int n = n0 + ty + j * 8;
        float v = tile[tx][ty + j * 8];
        __nv_bfloat16 hi, lo; split2(v, hi, lo);
        long long r = (long long)n * 3 * K;
        out[r + k0 + tx] = hi;
        out[r + K + k0 + tx] = hi;
        out[r + 2 * K + k0 + tx] = lo;
    }
}

// ============================ PE layer 1 -> split A ============================
__global__ void pe1_split(const float* __restrict__ pos, const float* __restrict__ w1,
                          const float* __restrict__ b1, __nv_bfloat16* __restrict__ out){
    long long idx = (long long)blockIdx.x * 256 + threadIdx.x;   // 8192*512
    int m = (int)(idx >> 9), c = (int)(idx & 511);
    float p0 = pos[m * 3], p1 = pos[m * 3 + 1], p2 = pos[m * 3 + 2];
    float v = gelu_f(p0 * w1[c] + p1 * w1[512 + c] + p2 * w1[1024 + c] + b1[c]);
    __nv_bfloat16 hi, lo; split2(v, hi, lo);
    __nv_bfloat16* o = out + (long long)m * 1536;
    o[c] = hi; o[512 + c] = lo; o[1024 + c] = hi;
}

// ============================ build q/k attention operands ============================
// q gets softmax scale folded in before split.
__global__ void qkbuild(const float* __restrict__ qkv, const float* __restrict__ pe,
                        __nv_bfloat16* __restrict__ qA, __nv_bfloat16* __restrict__ kB){
    long long idx = (long long)blockIdx.x * 256 + threadIdx.x;   // 16*4096*64
    int d = (int)(idx & 63);
    int n = (int)((idx >> 6) & 4095);
    int bh = (int)(idx >> 18);
    int b = bh >> 3, h = bh & 7;
    long long token = (long long)b * 4096 + n;
    long long qb = token * C3 + h * 64 + d;
    float pev = pe[token * 512 + h * 64 + d];
    float qv = (qkv[qb] + pev) * 0.125f;
    float kv = qkv[qb + 512] + pev;
    __nv_bfloat16 qh, ql, kh, kl;
    split2(qv, qh, ql); split2(kv, kh, kl);
    long long r = ((long long)bh * 4096 + n) * 192;
    qA[r + d] = qh; qA[r + 64 + d] = ql; qA[r + 128 + d] = qh;
    kB[r + d] = kh; kB[r + 64 + d] = kh; kB[r + 128 + d] = kl;
}

// ============================ build V^T operands (transpose + split) ============================
__global__ void vbuild(const float* __restrict__ qkv,
                       __nv_bfloat16* __restrict__ vBh, __nv_bfloat16* __restrict__ vBl){
    __shared__ float tile[32][33];
    int bh = blockIdx.z; int b = bh >> 3, h = bh & 7;
    int n0 = blockIdx.x * 32, d0 = blockIdx.y * 32;
    int tx = threadIdx.x, ty = threadIdx.y;
    #pragma unroll
    for (int j = 0; j < 4; j++){
        int n = n0 + ty + j * 8;
        tile[ty + j * 8][tx] = qkv[((long long)b * 4096 + n) * C3 + 1024 + h * 64 + d0 + tx];
    }
    __syncthreads();
    #pragma unroll
    for (int j = 0; j < 4; j++){
        int d = d0 + ty + j * 8;
        float v = tile[tx][ty + j * 8];
        __nv_bfloat16 hi, lo; split2(v, hi, lo);
        long long r = ((long long)bh * 64 + d) * 4096;
        vBh[r + n0 + tx] = hi;
        vBl[r + n0 + tx] = lo;
    }
}

// ============================ host ============================
extern "C" void kernel_launch(void* const* d_in, const int* in_sizes, int n_in,
                              void* d_out, int out_size){
    const float* x      = (const float*)d_in[0];
    const float* pos    = (const float*)d_in[1];
    const float* qkv_w  = (const float*)d_in[2];
    const float* qkv_b  = (const float*)d_in[3];
    const float* proj_w = (const float*)d_in[4];
    const float* proj_b = (const float*)d_in[5];
    const float* pe_w1  = (const float*)d_in[6];
    const float* pe_b1  = (const float*)d_in[7];
    const float* pe_w2  = (const float*)d_in[8];
    const float* pe_b2  = (const float*)d_in[9];
    const float* mlp_w1 = (const float*)d_in[10];
    const float* mlp_b1 = (const float*)d_in[11];
    const float* mlp_w2 = (const float*)d_in[12];
    const float* mlp_b2 = (const float*)d_in[13];
    const float* n1_g   = (const float*)d_in[14];
    const float* n1_b   = (const float*)d_in[15];
    const float* n2_g   = (const float*)d_in[16];
    const float* n2_b   = (const float*)d_in[17];
    float* out = (float*)d_out;

    __nv_bfloat16 *hA, *qA, *kB, *vBh, *vBl, *oA, *m1A;
    __nv_bfloat16 *qkvB, *pe2B, *projB, *mlp1B, *mlp2B;
    float *qkvf, *pef, *of, *x2f, *m1f;
    cudaGetSymbolAddress((void**)&hA,   g_hA);
    cudaGetSymbolAddress((void**)&qkvf, g_qkvf);
    cudaGetSymbolAddress((void**)&pef,  g_pef);
    cudaGetSymbolAddress((void**)&qA,   g_qA);
    cudaGetSymbolAddress((void**)&kB,   g_kB);
    cudaGetSymbolAddress((void**)&vBh,  g_vBh);
    cudaGetSymbolAddress((void**)&vBl,  g_vBl);
    cudaGetSymbolAddress((void**)&of,   g_of);
    cudaGetSymbolAddress((void**)&oA,   g_oA);
    cudaGetSymbolAddress((void**)&x2f,  g_x2f);
    cudaGetSymbolAddress((void**)&m1f,  g_m1f);
    cudaGetSymbolAddress((void**)&m1A,  g_m1A);
    cudaGetSymbolAddress((void**)&qkvB, g_qkvB);
    cudaGetSymbolAddress((void**)&pe2B, g_pe2B);
    cudaGetSymbolAddress((void**)&projB,g_projB);
    cudaGetSymbolAddress((void**)&mlp1B,g_mlp1B);
    cudaGetSymbolAddress((void**)&mlp2B,g_mlp2B);

    __nv_bfloat16* peA = m1A;   // disjoint lifetime

    cudaFuncSetAttribute(mmagemm,    cudaFuncAttributeMaxDynamicSharedMemorySize, DYN_SMEM);
    cudaFuncSetAttribute(flash_attn, cudaFuncAttributeMaxDynamicSharedMemorySize, FA_SMEM);

    dim3 tsb(32, 8);

    // weight transpose-splits
    tsplit<<<dim3(512/32, 1536/32), tsb>>>(qkv_w,  qkvB, 512, 1536);
    tsplit<<<dim3(512/32,  512/32), tsb>>>(pe_w2,  pe2B, 512, 512);
    tsplit<<<dim3(512/32,  512/32), tsb>>>(proj_w, projB, 512, 512);
    tsplit<<<dim3(512/32, 2048/32), tsb>>>(mlp_w1, mlp1B, 512, 2048);
    tsplit<<<dim3(2048/32, 512/32), tsb>>>(mlp_w2, mlp2B, 2048, 512);

    // 1. hA = split(LN1(x))
    ln_split<<<NTOK, 256>>>(x, n1_g, n1_b, hA);

    // 2. qkv = hA @ qkvB^T + qkv_b
    mmagemm<<<dim3(12, 64, 1), 256, DYN_SMEM>>>(
        hA, qkvB, qkv_b, nullptr, qkvf,
        1536, 1536, 1536, C3, C3, 0, 0, 0, 0, 1, 1.0f, 0);

    // 3. peA = split(gelu(pos @ pe_w1 + pe_b1))
    pe1_split<<<(NTOK*DIMC)/256, 256>>>(pos, pe_w1, pe_b1, peA);

    // 4. pe = peA @ pe2B^T + pe_b2
    mmagemm<<<dim3(4, 64, 1), 256, DYN_SMEM>>>(
        peA, pe2B, pe_b2, nullptr, pef,
        1536, 1536, 1536, DIMC, DIMC, 0, 0, 0, 0, 1, 1.0f, 0);

    // 5. build q/k split operands (pe + scale folded in)
    qkbuild<<<(16*4096*64)/256, 256>>>(qkvf, pef, qA, kB);

    // 6. build V^T operands
    vbuild<<<dim3(128, 2, 16), tsb>>>(qkvf, vBh, vBl);

    // 7. fused flash attention -> of
    flash_attn<<<dim3(32, 16), 256, FA_SMEM>>>(qA, kB, vBh, vBl, of);

    // 8. oA = split(o)
    splitA<<<(NTOK*DIMC)/256, 256>>>(of, oA, 512);

    // 9. x2 = x + oA @ projB^T + proj_b
    mmagemm<<<dim3(4, 64, 1), 256, DYN_SMEM>>>(
        oA, projB, proj_b, x, x2f,
        1536, 1536, 1536, DIMC, DIMC, 0, 0, 0, 0, 1, 1.0f, 2);

    // 10. hA = split(LN2(x2))
    ln_split<<<NTOK, 256>>>(x2f, n2_g, n2_b, hA);

    // 11. m1 = gelu(hA @ mlp1B^T + mlp_b1)
    mmagemm<<<dim3(16, 64, 1), 256, DYN_SMEM>>>(
        hA, mlp1B, mlp_b1, nullptr, m1f,
        1536, 1536, 1536, MLPH, MLPH, 0, 0, 0, 0, 1, 1.0f, 1);

    // 12. m1A = split(m1)
    splitA<<<(NTOK*MLPH)/256, 256>>>(m1f, m1A, 2048);

    // 13. out = x2 + m1A @ mlp2B^T + mlp_b2
    mmagemm<<<dim3(4, 64, 1), 256, DYN_SMEM>>>(
        m1A, mlp2B, mlp_b2, x2f, out,
        6144, 6144, 6144, DIMC, DIMC, 0, 0, 0, 0, 1, 1.0f, 2);
}

// round 7
// speedup vs baseline: 2.9105x; 1.1459x over previous
#include <cuda_runtime.h>
#include <cuda_bf16.h>
#include <math.h>
#include <stdint.h>

#define DIMC 512
#define NTOK 8192      // B*N
#define SEQ  4096
#define BATCH 2
#define HEADS 8
#define HD   64
#define MLPH 2048
#define BH   16        // BATCH*HEADS

// ============================ scratch buffers ============================
__device__ __align__(256) __nv_bfloat16 g_hA  [8192ULL*1536];   // ln out split A (hi|lo|hi)
__device__ __align__(256) float         g_pef [8192ULL*512];
__device__ __align__(256) __nv_bfloat16 g_qA  [16ULL*4096*192]; // q split (hi|lo|hi), scale folded
__device__ __align__(256) __nv_bfloat16 g_kB  [16ULL*4096*192]; // k split (hi|hi|lo)
__device__ __align__(256) __nv_bfloat16 g_vBh [16ULL*64*4096];  // V_hi transposed [bh][d][n]
__device__ __align__(256) __nv_bfloat16 g_vBl [16ULL*64*4096];  // V_lo transposed
__device__ __align__(256) __nv_bfloat16 g_oA  [8192ULL*1536];   // attn out split (hi|lo|hi)
__device__ __align__(256) float         g_x2f [8192ULL*512];
__device__ __align__(256) __nv_bfloat16 g_m1A [8192ULL*6144];   // mlp hidden split; also hosts peA early
__device__ __align__(256) __nv_bfloat16 g_qkvB [1536ULL*1536];  // weights (hi|hi|lo), transposed
__device__ __align__(256) __nv_bfloat16 g_pe2B [512ULL*1536];
__device__ __align__(256) __nv_bfloat16 g_projB[512ULL*1536];
__device__ __align__(256) __nv_bfloat16 g_mlp1B[2048ULL*1536];
__device__ __align__(256) __nv_bfloat16 g_mlp2B[512ULL*6144];

// ============================ helpers ============================
__device__ __forceinline__ uint32_t smem_u32(const void* p){
    uint32_t a;
    asm("{ .reg .u64 t; cvta.to.shared.u64 t, %1; cvt.u32.u64 %0, t; }" : "=r"(a) : "l"(p));
    return a;
}
__device__ __forceinline__ float gelu_f(float v){
    return 0.5f * v * (1.0f + erff(v * 0.70710678118654752440f));
}
__device__ __forceinline__ void split2(float x, __nv_bfloat16& hi, __nv_bfloat16& lo){
    hi = __float2bfloat16(x);
    lo = __float2bfloat16(x - __bfloat162float(hi));
}
__device__ __forceinline__ uint32_t packbf(float f0, float f1){
    __nv_bfloat162 t;
    t.x = __float2bfloat16(f0);
    t.y = __float2bfloat16(f1);
    return *(uint32_t*)&t;
}
__device__ __forceinline__ void cpasync16(uint32_t dst, const void* src, bool pred){
    asm volatile("cp.async.cg.shared.global [%0], [%1], 16, %2;"
                 :: "r"(dst), "l"(src), "r"(pred ? 16 : 0) : "memory");
}
#define CP_COMMIT()  asm volatile("cp.async.commit_group;" ::: "memory")
#define CP_WAIT(n)   asm volatile("cp.async.wait_group %0;" :: "n"(n) : "memory")

__device__ __forceinline__ void ldm_x4(uint32_t addr, uint32_t& r0, uint32_t& r1,
                                       uint32_t& r2, uint32_t& r3){
    asm volatile("ldmatrix.sync.aligned.m8n8.x4.shared.b16 {%0,%1,%2,%3}, [%4];"
                 : "=r"(r0), "=r"(r1), "=r"(r2), "=r"(r3) : "r"(addr));
}
__device__ __forceinline__ void mma16816(float* c, const uint32_t* a, const uint32_t* b){
    asm volatile("mma.sync.aligned.m16n8k16.row.col.f32.bf16.bf16.f32 "
                 "{%0,%1,%2,%3}, {%4,%5,%6,%7}, {%8,%9}, {%0,%1,%2,%3};"
                 : "+f"(c[0]), "+f"(c[1]), "+f"(c[2]), "+f"(c[3])
                 : "r"(a[0]), "r"(a[1]), "r"(a[2]), "r"(a[3]), "r"(b[0]), "r"(b[1]));
}

// ============================ GEMM common ============================
#define ROWB 144                 // smem row stride bytes (64 bf16 + 8 pad)
#define TBUF (128 * ROWB)        // 18432 bytes per tile buffer
#define DYN_SMEM (4 * TBUF)      // 73728

__device__ __forceinline__ void load_tile(const __nv_bfloat16* __restrict__ G, int ldE,
                                          int nrows, uint32_t smbase, int tid){
    #pragma unroll
    for (int i = 0; i < 4; i++){
        int id  = tid + i * 256;          // 0..1023
        int r   = id >> 3, c16 = id & 7;
        bool p  = r < nrows;
        const char* src = (const char*)(G + (long long)(p ? r : 0) * ldE) + c16 * 16;
        cpasync16(smbase + r * ROWB + c16 * 16, src, p);
    }
}

// mainloop shared by both GEMM kernels: accumulates 128x128 tile into acc.
__device__ __forceinline__ void gemm_mainloop(
    const __nv_bfloat16* __restrict__ A, const __nv_bfloat16* __restrict__ B,
    int Kp, int lda, int ldb, int NT, long long m0, long long n0,
    uint32_t smu, int tid, int lane, int wm, int wn, float acc[2][8][4])
{
    uint32_t asb[2] = { smu,        smu + 2 * TBUF };
    uint32_t bsb[2] = { smu + TBUF, smu + 3 * TBUF };
    int nc = Kp >> 6;
    load_tile(A + m0 * lda, lda, 128, asb[0], tid);
    load_tile(B + n0 * ldb, ldb, NT,  bsb[0], tid);
    CP_COMMIT();

    for (int c = 0; c < nc; c++){
        int cur = c & 1;
        if (c + 1 < nc){
            load_tile(A + m0 * lda + (c + 1) * 64, lda, 128, asb[cur ^ 1], tid);
            load_tile(B + n0 * ldb + (c + 1) * 64, ldb, NT,  bsb[cur ^ 1], tid);
            CP_COMMIT();
            CP_WAIT(1);
        } else {
            CP_WAIT(0);
        }
        __syncthreads();

        #pragma unroll
        for (int kk = 0; kk < 4; kk++){
            uint32_t afr[2][4], bfr[4][4];
            #pragma unroll
            for (int mt = 0; mt < 2; mt++){
                int row = wm + mt * 16 + (lane & 15);
                uint32_t addr = asb[cur] + row * ROWB + kk * 32 + ((lane >> 4) << 4);
                ldm_x4(addr, afr[mt][0], afr[mt][1], afr[mt][2], afr[mt][3]);
            }
            #pragma unroll
            for (int np = 0; np < 4; np++){
                int row = wn + np * 16 + ((lane & 7) | ((lane >> 4) << 3));
                uint32_t addr = bsb[cur] + row * ROWB + kk * 32 + (((lane >> 3) & 1) << 4);
                ldm_x4(addr, bfr[np][0], bfr[np][1], bfr[np][2], bfr[np][3]);
            }
            #pragma unroll
            for (int mt = 0; mt < 2; mt++)
                #pragma unroll
                for (int nt = 0; nt < 8; nt++)
                    mma16816(acc[mt][nt], afr[mt], &bfr[nt >> 1][(nt & 1) * 2]);
        }
        __syncthreads();
    }
}

// ============================ generic GEMM ============================
// C[M,Ntot] = A @ B^T (+bias)(gelu)(+res) -> fp32 C, OR split bf16 Cs3 (hi|lo|hi, width K3).
__global__ void __launch_bounds__(256, 2) mmagemm(
    const __nv_bfloat16* __restrict__ A, const __nv_bfloat16* __restrict__ B,
    const float* __restrict__ bias, const float* __restrict__ res,
    float* __restrict__ C, __nv_bfloat16* __restrict__ Cs3, int K3,
    int Kp, int lda, int ldb, int ldc, int Ntot, int epi)
{
    extern __shared__ char dynsm[];
    int tid = threadIdx.x, lane = tid & 31, w = tid >> 5;
    int wm = (w & 3) * 32, wn = (w >> 2) * 64;
    long long m0 = blockIdx.y * 128;
    long long n0 = blockIdx.x * 128;
    int NT = Ntot - (int)n0; if (NT > 128) NT = 128;
    uint32_t smu = smem_u32(dynsm);

    float acc[2][8][4];
    #pragma unroll
    for (int i = 0; i < 2; i++)
        #pragma unroll
        for (int j = 0; j < 8; j++)
            #pragma unroll
            for (int q = 0; q < 4; q++) acc[i][j][q] = 0.f;

    gemm_mainloop(A, B, Kp, lda, ldb, NT, m0, n0, smu, tid, lane, wm, wn, acc);

    float* Cs = (float*)dynsm;   // 128 x 132
    #pragma unroll
    for (int mt = 0; mt < 2; mt++)
        #pragma unroll
        for (int nt = 0; nt < 8; nt++){
            int r  = wm + mt * 16 + (lane >> 2);
            int cc = wn + nt * 8 + (lane & 3) * 2;
            Cs[r * 132 + cc]           = acc[mt][nt][0];
            Cs[r * 132 + cc + 1]       = acc[mt][nt][1];
            Cs[(r + 8) * 132 + cc]     = acc[mt][nt][2];
            Cs[(r + 8) * 132 + cc + 1] = acc[mt][nt][3];
        }
    __syncthreads();

    for (int e = tid; e < 128 * 128; e += 256){
        int rr = e >> 7, cc = e & 127;
        int gc = (int)n0 + cc;
        if (gc < Ntot){
            float v = Cs[rr * 132 + cc];
            if (bias)     v += bias[gc];
            if (epi & 1)  v  = gelu_f(v);
            long long mr = m0 + rr;
            if (Cs3){
                __nv_bfloat16 hi, lo; split2(v, hi, lo);
                __nv_bfloat16* o = Cs3 + mr * (3LL * K3);
                o[gc] = hi; o[K3 + gc] = lo; o[2 * K3 + gc] = hi;
            } else {
                long long ga = mr * ldc + gc;
                if (epi & 2) v += res[ga];
                C[ga] = v;
            }
        }
    }
}

// ============================ QKV GEMM with fused operand-build epilogue ============================
// Computes qkv = hA @ qkvB^T + bias, then directly emits split attention operands:
//   q (+pe, *0.125) -> qA [bh][n][hi|lo|hi], k (+pe) -> kB [bh][n][hi|hi|lo],
//   v -> vBh/vBl transposed [bh][d][n].
__global__ void __launch_bounds__(256, 2) qkv_gemm(
    const __nv_bfloat16* __restrict__ A, const __nv_bfloat16* __restrict__ B,
    const float* __restrict__ bias, const float* __restrict__ pe,
    __nv_bfloat16* __restrict__ qA, __nv_bfloat16* __restrict__ kB,
    __nv_bfloat16* __restrict__ vBh, __nv_bfloat16* __restrict__ vBl)
{
    extern __shared__ char dynsm[];
    int tid = threadIdx.x, lane = tid & 31, w = tid >> 5;
    int wm = (w & 3) * 32, wn = (w >> 2) * 64;
    long long m0 = blockIdx.y * 128;
    long long n0 = blockIdx.x * 128;
    uint32_t smu = smem_u32(dynsm);

    float acc[2][8][4];
    #pragma unroll
    for (int i = 0; i < 2; i++)
        #pragma unroll
        for (int j = 0; j < 8; j++)
            #pragma unroll
            for (int q = 0; q < 4; q++) acc[i][j][q] = 0.f;

    gemm_mainloop(A, B, 1536, 1536, 1536, 128, m0, n0, smu, tid, lane, wm, wn, acc);

    float* Cs = (float*)dynsm;   // 128 x 129 (odd stride: conflict-free col reads)
    #pragma unroll
    for (int mt = 0; mt < 2; mt++)
        #pragma unroll
        for (int nt = 0; nt < 8; nt++){
            int r  = wm + mt * 16 + (lane >> 2);
            int cc = wn + nt * 8 + (lane & 3) * 2;
            Cs[r * 129 + cc]           = acc[mt][nt][0];
            Cs[r * 129 + cc + 1]       = acc[mt][nt][1];
            Cs[(r + 8) * 129 + cc]     = acc[mt][nt][2];
            Cs[(r + 8) * 129 + cc + 1] = acc[mt][nt][3];
        }
    __syncthreads();

    int gtype = (int)(n0 >> 9);   // 0 q, 1 k, 2 v
    if (gtype < 2){
        for (int e = tid; e < 128 * 128; e += 256){
            int rr = e >> 7, cc = e & 127;
            int token = (int)m0 + rr;
            int c = ((int)n0 & 511) + cc;
            float val = Cs[rr * 129 + cc] + bias[(int)n0 + cc]
                      + pe[(long long)token * 512 + c];
            int bq = token >> 12, n = token & 4095;
            int h = c >> 6, d = c & 63;
            long long r = ((long long)(bq * 8 + h) * 4096 + n) * 192;
            __nv_bfloat16 hi, lo;
            if (gtype == 0){
                val *= 0.125f;
                split2(val, hi, lo);
                qA[r + d] = hi; qA[r + 64 + d] = lo; qA[r + 128 + d] = hi;
            } else {
                split2(val, hi, lo);
                kB[r + d] = hi; kB[r + 64 + d] = hi; kB[r + 128 + d] = lo;
            }
        }
    } else {
        for (int e = tid; e < 128 * 128; e += 256){
            int dl = e >> 7, rr = e & 127;          // column-major: coalesced n writes
            int token = (int)m0 + rr;
            int c = ((int)n0 & 511) + dl;
            float val = Cs[rr * 129 + dl] + bias[(int)n0 + dl];
            int bq = token >> 12, n = token & 4095;
            int h = c >> 6, d = c & 63;
            __nv_bfloat16 hi, lo; split2(val, hi, lo);
            long long r = ((long long)(bq * 8 + h) * 64 + d) * 4096 + n;
            vBh[r] = hi; vBl[r] = lo;
        }
    }
}

// ============================ flash attention ============================
#define QROWB 400
#define KROWB 400
#define VROWB 144
#define FA_QS   0
#define FA_KS   51200                       // + buf*25600
#define FA_VH   (51200 + 2*25600)           // + buf*9216
#define FA_VL   (FA_VH + 2*9216)
#define FA_SMEM (FA_VL + 2*9216)            // 139264

__device__ __forceinline__ void fa_load_kv(
    const __nv_bfloat16* __restrict__ kB, const __nv_bfloat16* __restrict__ vh,
    const __nv_bfloat16* __restrict__ vl,
    long long kbase, long long vbase, int c, uint32_t smu, int buf, int tid)
{
    uint32_t ks  = smu + FA_KS + buf * 25600;
    uint32_t vhs = smu + FA_VH + buf * 9216;
    uint32_t vls = smu + FA_VL + buf * 9216;
    #pragma unroll
    for (int i = 0; i < 6; i++){            // K: 64 rows x 384B
        int id = tid + i * 256;
        int r = id / 24, c16 = id % 24;
        cpasync16(ks + r * KROWB + c16 * 16,
                  kB + kbase + (long long)(c * 64 + r) * 192 + c16 * 8, true);
    }
    #pragma unroll
    for (int i = 0; i < 2; i++){            // V^T hi/lo: 64 rows x 128B each
        int id = tid + i * 256;
        int r = id >> 3, c16 = id & 7;
        cpasync16(vhs + r * VROWB + c16 * 16,
                  vh + vbase + (long long)r * 4096 + c * 64 + c16 * 8, true);
        cpasync16(vls + r * VROWB + c16 * 16,
                  vl + vbase + (long long)r * 4096 + c * 64 + c16 * 8, true);
    }
}

__global__ void __launch_bounds__(256, 1) flash_attn(
    const __nv_bfloat16* __restrict__ qA, const __nv_bfloat16* __restrict__ kB,
    const __nv_bfloat16* __restrict__ vh, const __nv_bfloat16* __restrict__ vl)
{
    extern __shared__ char dynsm[];
    uint32_t smu = smem_u32(dynsm);
    int tid = threadIdx.x, lane = tid & 31, w = tid >> 5;
    int bh = blockIdx.y;
    int b = bh >> 3, h = bh & 7;
    int m0 = blockIdx.x * 128;

    long long qbase = ((long long)bh * 4096 + m0) * 192;
    long long kbase = (long long)bh * 4096 * 192;
    long long vbase = (long long)bh * 64 * 4096;

    #pragma unroll
    for (int i = 0; i < 12; i++){           // Q: 128 rows x 384B
        int id = tid + i * 256;
        int r = id / 24, c16 = id % 24;
        cpasync16(smu + FA_QS + r * QROWB + c16 * 16,
                  qA + qbase + (long long)r * 192 + c16 * 8, true);
    }
    CP_COMMIT();
    fa_load_kv(kB, vh, vl, kbase, vbase, 0, smu, 0, tid);
    CP_COMMIT();
    CP_WAIT(1);
    __syncthreads();

    uint32_t qf[12][4];
    #pragma unroll
    for (int kk = 0; kk < 12; kk++){
        int row = w * 16 + (lane & 15);
        uint32_t addr = smu + FA_QS + row * QROWB + kk * 32 + ((lane >> 4) << 4);
        ldm_x4(addr, qf[kk][0], qf[kk][1], qf[kk][2], qf[kk][3]);
    }

    float O[8][4];
    #pragma unroll
    for (int i = 0; i < 8; i++)
        #pragma unroll
        for (int j = 0; j < 4; j++) O[i][j] = 0.f;
    float m0s = -1e30f, m1s = -1e30f, l0 = 0.f, l1 = 0.f;

    for (int c = 0; c < 64; c++){
        int buf = c & 1;
        if (c + 1 < 64){
            fa_load_kv(kB, vh, vl, kbase, vbase, c + 1, smu, buf ^ 1, tid);
            CP_COMMIT();
            CP_WAIT(1);
        } else {
            CP_WAIT(0);
        }
        __syncthreads();

        uint32_t ks  = smu + FA_KS + buf * 25600;
        uint32_t vhs = smu + FA_VH + buf * 9216;
        uint32_t vls = smu + FA_VL + buf * 9216;

        float S[8][4];
        #pragma unroll
        for (int i = 0; i < 8; i++)
            #pragma unroll
            for (int j = 0; j < 4; j++) S[i][j] = 0.f;
        #pragma unroll
        for (int kk = 0; kk < 12; kk++){
            uint32_t bfr[4][4];
            #pragma unroll
            for (int np = 0; np < 4; np++){
                int row = np * 16 + ((lane & 7) | ((lane >> 4) << 3));
                uint32_t addr = ks + row * KROWB + kk * 32 + (((lane >> 3) & 1) << 4);
                ldm_x4(addr, bfr[np][0], bfr[np][1], bfr[np][2], bfr[np][3]);
            }
            #pragma unroll
            for (int nt = 0; nt < 8; nt++)
                mma16816(S[nt], qf[kk], &bfr[nt >> 1][(nt & 1) * 2]);
        }

        float mx0 = -1e30f, mx1 = -1e30f;
        #pragma unroll
        for (int nt = 0; nt < 8; nt++){
            mx0 = fmaxf(mx0, fmaxf(S[nt][0], S[nt][1]));
            mx1 = fmaxf(mx1, fmaxf(S[nt][2], S[nt][3]));
        }
        mx0 = fmaxf(mx0, __shfl_xor_sync(0xffffffffu, mx0, 1));
        mx0 = fmaxf(mx0, __shfl_xor_sync(0xffffffffu, mx0, 2));
        mx1 = fmaxf(mx1, __shfl_xor_sync(0xffffffffu, mx1, 1));
        mx1 = fmaxf(mx1, __shfl_xor_sync(0xffffffffu, mx1, 2));
        float nm0 = fmaxf(m0s, mx0), nm1 = fmaxf(m1s, mx1);
        float sc0 = __expf(m0s - nm0), sc1 = __expf(m1s - nm1);
        float sum0 = 0.f, sum1 = 0.f;
        #pragma unroll
        for (int nt = 0; nt < 8; nt++){
            S[nt][0] = __expf(S[nt][0] - nm0); sum0 += S[nt][0];
            S[nt][1] = __expf(S[nt][1] - nm0); sum0 += S[nt][1];
            S[nt][2] = __expf(S[nt][2] - nm1); sum1 += S[nt][2];
            S[nt][3] = __expf(S[nt][3] - nm1); sum1 += S[nt][3];
        }
        sum0 += __shfl_xor_sync(0xffffffffu, sum0, 1);
        sum0 += __shfl_xor_sync(0xffffffffu, sum0, 2);
        sum1 += __shfl_xor_sync(0xffffffffu, sum1, 1);
        sum1 += __shfl_xor_sync(0xffffffffu, sum1, 2);
        l0 = l0 * sc0 + sum0; l1 = l1 * sc1 + sum1;
        m0s = nm0; m1s = nm1;
        #pragma unroll
        for (int nt = 0; nt < 8; nt++){
            O[nt][0] *= sc0; O[nt][1] *= sc0;
            O[nt][2] *= sc1; O[nt][3] *= sc1;
        }

        #pragma unroll
        for (int kc = 0; kc < 4; kc++){
            uint32_t ph[4], pl[4];
            {
                int ta = 2 * kc, tb = 2 * kc + 1;
                ph[0] = packbf(S[ta][0], S[ta][1]);
                ph[1] = packbf(S[ta][2], S[ta][3]);
                ph[2] = packbf(S[tb][0], S[tb][1]);
                ph[3] = packbf(S[tb][2], S[tb][3]);
                __nv_bfloat162* hp;
                hp = (__nv_bfloat162*)&ph[0];
                pl[0] = packbf(S[ta][0] - __bfloat162float(hp->x), S[ta][1] - __bfloat162float(hp->y));
                hp = (__nv_bfloat162*)&ph[1];
                pl[1] = packbf(S[ta][2] - __bfloat162float(hp->x), S[ta][3] - __bfloat162float(hp->y));
                hp = (__nv_bfloat162*)&ph[2];
                pl[2] = packbf(S[tb][0] - __bfloat162float(hp->x), S[tb][1] - __bfloat162float(hp->y));
                hp = (__nv_bfloat162*)&ph[3];
                pl[3] = packbf(S[tb][2] - __bfloat162float(hp->x), S[tb][3] - __bfloat162float(hp->y));
            }
            uint32_t vhf[4][4], vlf[4][4];
            #pragma unroll
            for (int np = 0; np < 4; np++){
                int row = np * 16 + ((lane & 7) | ((lane >> 4) << 3));
                uint32_t col = kc * 32 + (((lane >> 3) & 1) << 4);
                ldm_x4(vhs + row * VROWB + col, vhf[np][0], vhf[np][1], vhf[np][2], vhf[np][3]);
                ldm_x4(vls + row * VROWB + col, vlf[np][0], vlf[np][1], vlf[np][2], vlf[np][3]);
            }
            #pragma unroll
            for (int nt = 0; nt < 8; nt++){
                mma16816(O[nt], ph, &vhf[nt >> 1][(nt & 1) * 2]);
                mma16816(O[nt], pl, &vhf[nt >> 1][(nt & 1) * 2]);
                mma16816(O[nt], ph, &vlf[nt >> 1][(nt & 1) * 2]);
            }
        }
        __syncthreads();
    }

    // ---- write O directly as split oA (hi|lo|hi) ----
    float inv0 = 1.0f / l0, inv1 = 1.0f / l1;
    int r0 = w * 16 + (lane >> 2);
    int col = (lane & 3) * 2;
    long long tok0 = (long long)b * 4096 + m0 + r0;
    #pragma unroll
    for (int nt = 0; nt < 8; nt++){
        int d = nt * 8 + col;
        float v00 = O[nt][0] * inv0, v01 = O[nt][1] * inv0;
        float v10 = O[nt][2] * inv1, v11 = O[nt][3] * inv1;
        __nv_bfloat16 h0a, l0a, h0b, l0b, h1a, l1a, h1b, l1b;
        split2(v00, h0a, l0a); split2(v01, h0b, l0b);
        split2(v10, h1a, l1a); split2(v11, h1b, l1b);
        __nv_bfloat162 hp0; hp0.x = h0a; hp0.y = h0b;
        __nv_bfloat162 lp0; lp0.x = l0a; lp0.y = l0b;
        __nv_bfloat162 hp1; hp1.x = h1a; hp1.y = h1b;
        __nv_bfloat162 lp1; lp1.x = l1a; lp1.y = l1b;
        __nv_bfloat16* o0 = g_oA + tok0 * 1536 + h * 64 + d;
        __nv_bfloat16* o1 = g_oA + (tok0 + 8) * 1536 + h * 64 + d;
        *(__nv_bfloat162*)(o0)         = hp0;
        *(__nv_bfloat162*)(o0 + 512)   = lp0;
        *(__nv_bfloat162*)(o0 + 1024)  = hp0;
        *(__nv_bfloat162*)(o1)         = hp1;
        *(__nv_bfloat162*)(o1 + 512)   = lp1;
        *(__nv_bfloat162*)(o1 + 1024)  = hp1;
    }
}

// ============================ LayerNorm -> split A ============================
__global__ void ln_split(const float* __restrict__ x, const float* __restrict__ g,
                         const float* __restrict__ beta, __nv_bfloat16* __restrict__ y){
    long long row = blockIdx.x;
    const float* xr = x + row * DIMC;
    int t = threadIdx.x;
    float a0 = xr[t], a1 = xr[t + 256];
    float s  = a0 + a1, ss = a0 * a0 + a1 * a1;
    #pragma unroll
    for (int o = 16; o > 0; o >>= 1){
        s  += __shfl_xor_sync(0xffffffffu, s,  o);
        ss += __shfl_xor_sync(0xffffffffu, ss, o);
    }
    __shared__ float s1[8], s2[8];
    if ((t & 31) == 0){ s1[t >> 5] = s; s2[t >> 5] = ss; }
    __syncthreads();
    float tot = 0.f, tot2 = 0.f;
    #pragma unroll
    for (int i = 0; i < 8; i++){ tot += s1[i]; tot2 += s2[i]; }
    float mu  = tot * (1.0f / DIMC);
    float var = tot2 * (1.0f / DIMC) - mu * mu;
    float rsv = rsqrtf(var + 1e-5f);
    __nv_bfloat16* yr = y + row * (3 * DIMC);
    float y0 = (a0 - mu) * rsv * g[t] + beta[t];
    float y1 = (a1 - mu) * rsv * g[t + 256] + beta[t + 256];
    __nv_bfloat16 h0, l0, h1, l1;
    split2(y0, h0, l0); split2(y1, h1, l1);
    yr[t] = h0;  yr[512 + t] = l0;  yr[1024 + t] = h0;
    yr[t + 256] = h1; yr[512 + t + 256] = l1; yr[1024 + t + 256] = h1;
}

// ============================ weight transpose-split (B pattern hi|hi|lo) ============================
__global__ void tsplit(const float* __restrict__ W, __nv_bfloat16* __restrict__ out, int K, int N){
    __shared__ float tile[32][33];
    int k0 = blockIdx.x * 32, n0 = blockIdx.y * 32;
    int tx = threadIdx.x, ty = threadIdx.y;
    #pragma unroll
    for (int j = 0; j < 4; j++)
        tile[ty + j * 8][tx] = W[(long long)(k0 + ty + j * 8) * N + n0 + tx];
    __syncthreads();
    #pragma unroll
    for (int j = 0; j < 4; j++){
        int n = n0 + ty + j * 8;
        float v = tile[tx][ty + j * 8];
        __nv_bfloat16 hi, lo; split2(v, hi, lo);
        long long r = (long long)n * 3 * K;
        out[r + k0 + tx] = hi;
        out[r + K + k0 + tx] = hi;
        out[r + 2 * K + k0 + tx] = lo;
    }
}

// ============================ PE layer 1 -> split A ============================
__global__ void pe1_split(const float* __restrict__ pos, const float* __restrict__ w1,
                          const float* __restrict__ b1, __nv_bfloat16* __restrict__ out){
    long long idx = (long long)blockIdx.x * 256 + threadIdx.x;   // 8192*512
    int m = (int)(idx >> 9), c = (int)(idx & 511);
    float p0 = pos[m * 3], p1 = pos[m * 3 + 1], p2 = pos[m * 3 + 2];
    float v = gelu_f(p0 * w1[c] + p1 * w1[512 + c] + p2 * w1[1024 + c] + b1[c]);
    __nv_bfloat16 hi, lo; split2(v, hi, lo);
    __nv_bfloat16* o = out + (long long)m * 1536;
    o[c] = hi; o[512 + c] = lo; o[1024 + c] = hi;
}

// ============================ host ============================
extern "C" void kernel_launch(void* const* d_in, const int* in_sizes, int n_in,
                              void* d_out, int out_size){
    const float* x      = (const float*)d_in[0];
    const float* pos    = (const float*)d_in[1];
    const float* qkv_w  = (const float*)d_in[2];
    const float* qkv_b  = (const float*)d_in[3];
    const float* proj_w = (const float*)d_in[4];
    const float* proj_b = (const float*)d_in[5];
    const float* pe_w1  = (const float*)d_in[6];
    const float* pe_b1  = (const float*)d_in[7];
    const float* pe_w2  = (const float*)d_in[8];
    const float* pe_b2  = (const float*)d_in[9];
    const float* mlp_w1 = (const float*)d_in[10];
    const float* mlp_b1 = (const float*)d_in[11];
    const float* mlp_w2 = (const float*)d_in[12];
    const float* mlp_b2 = (const float*)d_in[13];
    const float* n1_g   = (const float*)d_in[14];
    const float* n1_b   = (const float*)d_in[15];
    const float* n2_g   = (const float*)d_in[16];
    const float* n2_b   = (const float*)d_in[17];
    float* out = (float*)d_out;

    __nv_bfloat16 *hA, *qA, *kB, *vBh, *vBl, *oA, *m1A;
    __nv_bfloat16 *qkvB, *pe2B, *projB, *mlp1B, *mlp2B;
    float *pef, *x2f;
    cudaGetSymbolAddress((void**)&hA,   g_hA);
    cudaGetSymbolAddress((void**)&pef,  g_pef);
    cudaGetSymbolAddress((void**)&qA,   g_qA);
    cudaGetSymbolAddress((void**)&kB,   g_kB);
    cudaGetSymbolAddress((void**)&vBh,  g_vBh);
    cudaGetSymbolAddress((void**)&vBl,  g_vBl);
    cudaGetSymbolAddress((void**)&oA,   g_oA);
    cudaGetSymbolAddress((void**)&x2f,  g_x2f);
    cudaGetSymbolAddress((void**)&m1A,  g_m1A);
    cudaGetSymbolAddress((void**)&qkvB, g_qkvB);
    cudaGetSymbolAddress((void**)&pe2B, g_pe2B);
    cudaGetSymbolAddress((void**)&projB,g_projB);
    cudaGetSymbolAddress((void**)&mlp1B,g_mlp1B);
    cudaGetSymbolAddress((void**)&mlp2B,g_mlp2B);

    __nv_bfloat16* peA = m1A;   // disjoint lifetime

    cudaFuncSetAttribute(mmagemm,    cudaFuncAttributeMaxDynamicSharedMemorySize, DYN_SMEM);
    cudaFuncSetAttribute(qkv_gemm,   cudaFuncAttributeMaxDynamicSharedMemorySize, DYN_SMEM);
    cudaFuncSetAttribute(flash_attn, cudaFuncAttributeMaxDynamicSharedMemorySize, FA_SMEM);

    dim3 tsb(32, 8);

    // weight transpose-splits
    tsplit<<<dim3(512/32, 1536/32), tsb>>>(qkv_w,  qkvB, 512, 1536);
    tsplit<<<dim3(512/32,  512/32), tsb>>>(pe_w2,  pe2B, 512, 512);
    tsplit<<<dim3(512/32,  512/32), tsb>>>(proj_w, projB, 512, 512);
    tsplit<<<dim3(512/32, 2048/32), tsb>>>(mlp_w1, mlp1B, 512, 2048);
    tsplit<<<dim3(2048/32, 512/32), tsb>>>(mlp_w2, mlp2B, 2048, 512);

    // 1. peA = split(gelu(pos @ pe_w1 + pe_b1)); pe = peA @ pe2B^T + pe_b2
    pe1_split<<<(NTOK*DIMC)/256, 256>>>(pos, pe_w1, pe_b1, peA);
    mmagemm<<<dim3(4, 64, 1), 256, DYN_SMEM>>>(
        peA, pe2B, pe_b2, nullptr, pef, nullptr, 0,
        1536, 1536, 1536, DIMC, DIMC, 0);

    // 2. hA = split(LN1(x))
    ln_split<<<NTOK, 256>>>(x, n1_g, n1_b, hA);

    // 3. qkv GEMM with fused operand construction
    qkv_gemm<<<dim3(12, 64, 1), 256, DYN_SMEM>>>(
        hA, qkvB, qkv_b, pef, qA, kB, vBh, vBl);

    // 4. fused flash attention -> oA (split)
    flash_attn<<<dim3(32, 16), 256, FA_SMEM>>>(qA, kB, vBh, vBl);

    // 5. x2 = x + oA @ projB^T + proj_b
    mmagemm<<<dim3(4, 64, 1), 256, DYN_SMEM>>>(
        oA, projB, proj_b, x, x2f, nullptr, 0,
        1536, 1536, 1536, DIMC, DIMC, 2);

    // 6. hA = split(LN2(x2))
    ln_split<<<NTOK, 256>>>(x2f, n2_g, n2_b, hA);

    // 7. m1A = split(gelu(hA @ mlp1B^T + mlp_b1))   (fused split epilogue)
    mmagemm<<<dim3(16, 64, 1), 256, DYN_SMEM>>>(
        hA, mlp1B, mlp_b1, nullptr, nullptr, m1A, 2048,
        1536, 1536, 1536, 0, MLPH, 1);

    // 8. out = x2 + m1A @ mlp2B^T + mlp_b2
    mmagemm<<<dim3(4, 64, 1), 256, DYN_SMEM>>>(
        m1A, mlp2B, mlp_b2, x2f, out, nullptr, 0,
        6144, 6144, 6144, DIMC, DIMC, 2);
}

// round 8
// speedup vs baseline: 6.9102x; 2.3742x over previous
#include <cuda_runtime.h>
#include <cuda_fp16.h>
#include <math.h>
#include <stdint.h>

#define DIMC 512
#define NTOK 8192      // B*N
#define SEQ  4096
#define HEADS 8
#define MLPH 2048
#define BH   16

// ============================ scratch buffers (fp16 single precision operands) ============================
__device__ __align__(256) __half g_hW  [8192ULL*512];    // ln out
__device__ __align__(256) float  g_pef [8192ULL*512];
__device__ __align__(256) __half g_qA  [16ULL*4096*64];  // q (scale folded) [bh][n][d]
__device__ __align__(256) __half g_kW  [16ULL*4096*64];  // k [bh][n][d]
__device__ __align__(256) __half g_vT  [16ULL*64*4096];  // V transposed [bh][d][n]
__device__ __align__(256) __half g_oW  [8192ULL*512];    // attn out
__device__ __align__(256) float  g_x2f [8192ULL*512];
__device__ __align__(256) __half g_m1W [8192ULL*2048];   // mlp hidden; also hosts peW early
__device__ __align__(256) __half g_qkvB [1536ULL*512];   // weights transposed [N][K]
__device__ __align__(256) __half g_pe2B [512ULL*512];
__device__ __align__(256) __half g_projB[512ULL*512];
__device__ __align__(256) __half g_mlp1B[2048ULL*512];
__device__ __align__(256) __half g_mlp2B[512ULL*2048];

// ============================ helpers ============================
__device__ __forceinline__ uint32_t smem_u32(const void* p){
    uint32_t a;
    asm("{ .reg .u64 t; cvta.to.shared.u64 t, %1; cvt.u32.u64 %0, t; }" : "=r"(a) : "l"(p));
    return a;
}
__device__ __forceinline__ float gelu_f(float v){
    return 0.5f * v * (1.0f + erff(v * 0.70710678118654752440f));
}
__device__ __forceinline__ uint32_t packh(float a, float b){
    __half2 t = __floats2half2_rn(a, b);
    return *(uint32_t*)&t;
}
__device__ __forceinline__ void cpasync16(uint32_t dst, const void* src, bool pred){
    asm volatile("cp.async.cg.shared.global [%0], [%1], 16, %2;"
                 :: "r"(dst), "l"(src), "r"(pred ? 16 : 0) : "memory");
}
#define CP_COMMIT()  asm volatile("cp.async.commit_group;" ::: "memory")
#define CP_WAIT(n)   asm volatile("cp.async.wait_group %0;" :: "n"(n) : "memory")

__device__ __forceinline__ void ldm_x4(uint32_t addr, uint32_t& r0, uint32_t& r1,
                                       uint32_t& r2, uint32_t& r3){
    asm volatile("ldmatrix.sync.aligned.m8n8.x4.shared.b16 {%0,%1,%2,%3}, [%4];"
                 : "=r"(r0), "=r"(r1), "=r"(r2), "=r"(r3) : "r"(addr));
}
__device__ __forceinline__ void mma16816(float* c, const uint32_t* a, const uint32_t* b){
    asm volatile("mma.sync.aligned.m16n8k16.row.col.f32.f16.f16.f32 "
                 "{%0,%1,%2,%3}, {%4,%5,%6,%7}, {%8,%9}, {%0,%1,%2,%3};"
                 : "+f"(c[0]), "+f"(c[1]), "+f"(c[2]), "+f"(c[3])
                 : "r"(a[0]), "r"(a[1]), "r"(a[2]), "r"(a[3]), "r"(b[0]), "r"(b[1]));
}

// ============================ GEMM common ============================
#define ROWB 144                 // smem row stride bytes (64 fp16 + 8 pad)
#define TBUF (128 * ROWB)        // 18432 bytes per tile buffer
#define DYN_SMEM (4 * TBUF)      // 73728

__device__ __forceinline__ void load_tile(const __half* __restrict__ G, int ldE,
                                          uint32_t smbase, int tid){
    #pragma unroll
    for (int i = 0; i < 4; i++){
        int id  = tid + i * 256;          // 0..1023
        int r   = id >> 3, c16 = id & 7;
        const char* src = (const char*)(G + (long long)r * ldE) + c16 * 16;
        cpasync16(smbase + r * ROWB + c16 * 16, src, true);
    }
}

// 128x128 tile accumulate over K, BK=64, double buffered
__device__ __forceinline__ void gemm_mainloop(
    const __half* __restrict__ A, const __half* __restrict__ B,
    int Kp, int lda, int ldb, long long m0, long long n0,
    uint32_t smu, int tid, int lane, int wm, int wn, float acc[2][8][4])
{
    uint32_t asb[2] = { smu,        smu + 2 * TBUF };
    uint32_t bsb[2] = { smu + TBUF, smu + 3 * TBUF };
    int nc = Kp >> 6;
    load_tile(A + m0 * lda, lda, asb[0], tid);
    load_tile(B + n0 * ldb, ldb, bsb[0], tid);
    CP_COMMIT();

    for (int c = 0; c < nc; c++){
        int cur = c & 1;
        if (c + 1 < nc){
            load_tile(A + m0 * lda + (c + 1) * 64, lda, asb[cur ^ 1], tid);
            load_tile(B + n0 * ldb + (c + 1) * 64, ldb, bsb[cur ^ 1], tid);
            CP_COMMIT();
            CP_WAIT(1);
        } else {
            CP_WAIT(0);
        }
        __syncthreads();

        #pragma unroll
        for (int kk = 0; kk < 4; kk++){
            uint32_t afr[2][4], bfr[4][4];
            #pragma unroll
            for (int mt = 0; mt < 2; mt++){
                int row = wm + mt * 16 + (lane & 15);
                uint32_t addr = asb[cur] + row * ROWB + kk * 32 + ((lane >> 4) << 4);
                ldm_x4(addr, afr[mt][0], afr[mt][1], afr[mt][2], afr[mt][3]);
            }
            #pragma unroll
            for (int np = 0; np < 4; np++){
                int row = wn + np * 16 + ((lane & 7) | ((lane >> 4) << 3));
                uint32_t addr = bsb[cur] + row * ROWB + kk * 32 + (((lane >> 3) & 1) << 4);
                ldm_x4(addr, bfr[np][0], bfr[np][1], bfr[np][2], bfr[np][3]);
            }
            #pragma unroll
            for (int mt = 0; mt < 2; mt++)
                #pragma unroll
                for (int nt = 0; nt < 8; nt++)
                    mma16816(acc[mt][nt], afr[mt], &bfr[nt >> 1][(nt & 1) * 2]);
        }
        __syncthreads();
    }
}

// ============================ generic GEMM ============================
// C[M,Ntot] = A @ B^T (+bias)(gelu)(+res) -> fp32 C or fp16 Ch (both stride ldc).
__global__ void __launch_bounds__(256, 2) mmagemm(
    const __half* __restrict__ A, const __half* __restrict__ B,
    const float* __restrict__ bias, const float* __restrict__ res,
    float* __restrict__ C, __half* __restrict__ Ch,
    int Kp, int lda, int ldb, int ldc, int epi)
{
    extern __shared__ char dynsm[];
    int tid = threadIdx.x, lane = tid & 31, w = tid >> 5;
    int wm = (w & 3) * 32, wn = (w >> 2) * 64;
    long long m0 = blockIdx.y * 128;
    long long n0 = blockIdx.x * 128;
    uint32_t smu = smem_u32(dynsm);

    float acc[2][8][4];
    #pragma unroll
    for (int i = 0; i < 2; i++)
        #pragma unroll
        for (int j = 0; j < 8; j++)
            #pragma unroll
            for (int q = 0; q < 4; q++) acc[i][j][q] = 0.f;

    gemm_mainloop(A, B, Kp, lda, ldb, m0, n0, smu, tid, lane, wm, wn, acc);

    float* Cs = (float*)dynsm;   // 128 x 132
    #pragma unroll
    for (int mt = 0; mt < 2; mt++)
        #pragma unroll
        for (int nt = 0; nt < 8; nt++){
            int r  = wm + mt * 16 + (lane >> 2);
            int cc = wn + nt * 8 + (lane & 3) * 2;
            Cs[r * 132 + cc]           = acc[mt][nt][0];
            Cs[r * 132 + cc + 1]       = acc[mt][nt][1];
            Cs[(r + 8) * 132 + cc]     = acc[mt][nt][2];
            Cs[(r + 8) * 132 + cc + 1] = acc[mt][nt][3];
        }
    __syncthreads();

    for (int e = tid; e < 128 * 128; e += 256){
        int rr = e >> 7, cc = e & 127;
        int gc = (int)n0 + cc;
        float v = Cs[rr * 132 + cc];
        if (bias)     v += bias[gc];
        if (epi & 1)  v  = gelu_f(v);
        long long ga = (m0 + rr) * ldc + gc;
        if (Ch){
            Ch[ga] = __float2half(v);
        } else {
            if (epi & 2) v += res[ga];
            C[ga] = v;
        }
    }
}

// ============================ QKV GEMM with fused operand-build epilogue ============================
// qkv = hW @ qkvB^T + bias; q(+pe,*0.125)->qA, k(+pe)->kW, v->vT (transposed).
__global__ void __launch_bounds__(256, 2) qkv_gemm(
    const __half* __restrict__ A, const __half* __restrict__ B,
    const float* __restrict__ bias, const float* __restrict__ pe,
    __half* __restrict__ qA, __half* __restrict__ kW, __half* __restrict__ vT)
{
    extern __shared__ char dynsm[];
    int tid = threadIdx.x, lane = tid & 31, w = tid >> 5;
    int wm = (w & 3) * 32, wn = (w >> 2) * 64;
    long long m0 = blockIdx.y * 128;
    long long n0 = blockIdx.x * 128;
    uint32_t smu = smem_u32(dynsm);

    float acc[2][8][4];
    #pragma unroll
    for (int i = 0; i < 2; i++)
        #pragma unroll
        for (int j = 0; j < 8; j++)
            #pragma unroll
            for (int q = 0; q < 4; q++) acc[i][j][q] = 0.f;

    gemm_mainloop(A, B, 512, 512, 512, m0, n0, smu, tid, lane, wm, wn, acc);

    float* Cs = (float*)dynsm;   // 128 x 129 (odd stride: conflict-free col reads)
    #pragma unroll
    for (int mt = 0; mt < 2; mt++)
        #pragma unroll
        for (int nt = 0; nt < 8; nt++){
            int r  = wm + mt * 16 + (lane >> 2);
            int cc = wn + nt * 8 + (lane & 3) * 2;
            Cs[r * 129 + cc]           = acc[mt][nt][0];
            Cs[r * 129 + cc + 1]       = acc[mt][nt][1];
            Cs[(r + 8) * 129 + cc]     = acc[mt][nt][2];
            Cs[(r + 8) * 129 + cc + 1] = acc[mt][nt][3];
        }
    __syncthreads();

    int gtype = (int)(n0 >> 9);   // 0 q, 1 k, 2 v
    if (gtype < 2){
        for (int e = tid; e < 128 * 128; e += 256){
            int rr = e >> 7, cc = e & 127;
            int token = (int)m0 + rr;
            int c = ((int)n0 & 511) + cc;
            float val = Cs[rr * 129 + cc] + bias[(int)n0 + cc]
                      + pe[(long long)token * 512 + c];
            int bq = token >> 12, n = token & 4095;
            int h = c >> 6, d = c & 63;
            long long r = ((long long)(bq * 8 + h) * 4096 + n) * 64 + d;
            if (gtype == 0) qA[r] = __float2half(val * 0.125f);
            else            kW[r] = __float2half(val);
        }
    } else {
        for (int e = tid; e < 128 * 128; e += 256){
            int dl = e >> 7, rr = e & 127;          // column-major: coalesced n writes
            int token = (int)m0 + rr;
            int c = ((int)n0 & 511) + dl;
            float val = Cs[rr * 129 + dl] + bias[(int)n0 + dl];
            int bq = token >> 12, n = token & 4095;
            int h = c >> 6, d = c & 63;
            vT[((long long)(bq * 8 + h) * 64 + d) * 4096 + n] = __float2half(val);
        }
    }
}

// ============================ flash attention (single fp16 operands) ============================
#define QROWB 144
#define KROWB 144
#define VROWB 144
#define FA_QS   0
#define FA_KS   18432                       // + buf*9216
#define FA_VS   (18432 + 2*9216)            // + buf*9216
#define FA_SMEM (FA_VS + 2*9216)            // 55296

__device__ __forceinline__ void fa_load_kv(
    const __half* __restrict__ kW, const __half* __restrict__ vT,
    long long kbase, long long vbase, int c, uint32_t smu, int buf, int tid)
{
    uint32_t ks = smu + FA_KS + buf * 9216;
    uint32_t vs = smu + FA_VS + buf * 9216;
    #pragma unroll
    for (int i = 0; i < 2; i++){            // K: 64 rows x 128B
        int id = tid + i * 256;
        int r = id >> 3, c16 = id & 7;
        cpasync16(ks + r * KROWB + c16 * 16,
                  kW + kbase + (long long)(c * 64 + r) * 64 + c16 * 8, true);
    }
    #pragma unroll
    for (int i = 0; i < 2; i++){            // V^T: 64 d-rows x 128B
        int id = tid + i * 256;
        int r = id >> 3, c16 = id & 7;
        cpasync16(vs + r * VROWB + c16 * 16,
                  vT + vbase + (long long)r * 4096 + c * 64 + c16 * 8, true);
    }
}

__global__ void __launch_bounds__(256, 2) flash_attn(
    const __half* __restrict__ qA, const __half* __restrict__ kW,
    const __half* __restrict__ vT, __half* __restrict__ oW)
{
    extern __shared__ char dynsm[];
    uint32_t smu = smem_u32(dynsm);
    int tid = threadIdx.x, lane = tid & 31, w = tid >> 5;
    int bh = blockIdx.y;
    int b = bh >> 3, h = bh & 7;
    int m0 = blockIdx.x * 128;

    long long qbase = ((long long)bh * 4096 + m0) * 64;
    long long kbase = (long long)bh * 4096 * 64;
    long long vbase = (long long)bh * 64 * 4096;

    #pragma unroll
    for (int i = 0; i < 4; i++){            // Q: 128 rows x 128B
        int id = tid + i * 256;
        int r = id >> 3, c16 = id & 7;
        cpasync16(smu + FA_QS + r * QROWB + c16 * 16,
                  qA + qbase + (long long)r * 64 + c16 * 8, true);
    }
    CP_COMMIT();
    fa_load_kv(kW, vT, kbase, vbase, 0, smu, 0, tid);
    CP_COMMIT();
    CP_WAIT(1);
    __syncthreads();

    uint32_t qf[4][4];
    #pragma unroll
    for (int kk = 0; kk < 4; kk++){
        int row = w * 16 + (lane & 15);
        uint32_t addr = smu + FA_QS + row * QROWB + kk * 32 + ((lane >> 4) << 4);
        ldm_x4(addr, qf[kk][0], qf[kk][1], qf[kk][2], qf[kk][3]);
    }

    float O[8][4];
    #pragma unroll
    for (int i = 0; i < 8; i++)
        #pragma unroll
        for (int j = 0; j < 4; j++) O[i][j] = 0.f;
    float m0s = -1e30f, m1s = -1e30f, l0 = 0.f, l1 = 0.f;

    for (int c = 0; c < 64; c++){
        int buf = c & 1;
        if (c + 1 < 64){
            fa_load_kv(kW, vT, kbase, vbase, c + 1, smu, buf ^ 1, tid);
            CP_COMMIT();
            CP_WAIT(1);
        } else {
            CP_WAIT(0);
        }
        __syncthreads();

        uint32_t ks = smu + FA_KS + buf * 9216;
        uint32_t vs = smu + FA_VS + buf * 9216;

        float S[8][4];
        #pragma unroll
        for (int i = 0; i < 8; i++)
            #pragma unroll
            for (int j = 0; j < 4; j++) S[i][j] = 0.f;
        #pragma unroll
        for (int kk = 0; kk < 4; kk++){
            uint32_t bfr[4][4];
            #pragma unroll
            for (int np = 0; np < 4; np++){
                int row = np * 16 + ((lane & 7) | ((lane >> 4) << 3));
                uint32_t addr = ks + row * KROWB + kk * 32 + (((lane >> 3) & 1) << 4);
                ldm_x4(addr, bfr[np][0], bfr[np][1], bfr[np][2], bfr[np][3]);
            }
            #pragma unroll
            for (int nt = 0; nt < 8; nt++)
                mma16816(S[nt], qf[kk], &bfr[nt >> 1][(nt & 1) * 2]);
        }

        float mx0 = -1e30f, mx1 = -1e30f;
        #pragma unroll
        for (int nt = 0; nt < 8; nt++){
            mx0 = fmaxf(mx0, fmaxf(S[nt][0], S[nt][1]));
            mx1 = fmaxf(mx1, fmaxf(S[nt][2], S[nt][3]));
        }
        mx0 = fmaxf(mx0, __shfl_xor_sync(0xffffffffu, mx0, 1));
        mx0 = fmaxf(mx0, __shfl_xor_sync(0xffffffffu, mx0, 2));
        mx1 = fmaxf(mx1, __shfl_xor_sync(0xffffffffu, mx1, 1));
        mx1 = fmaxf(mx1, __shfl_xor_sync(0xffffffffu, mx1, 2));
        float nm0 = fmaxf(m0s, mx0), nm1 = fmaxf(m1s, mx1);
        float sc0 = __expf(m0s - nm0), sc1 = __expf(m1s - nm1);
        float sum0 = 0.f, sum1 = 0.f;
        #pragma unroll
        for (int nt = 0; nt < 8; nt++){
            S[nt][0] = __expf(S[nt][0] - nm0); sum0 += S[nt][0];
            S[nt][1] = __expf(S[nt][1] - nm0); sum0 += S[nt][1];
            S[nt][2] = __expf(S[nt][2] - nm1); sum1 += S[nt][2];
            S[nt][3] = __expf(S[nt][3] - nm1); sum1 += S[nt][3];
        }
        sum0 += __shfl_xor_sync(0xffffffffu, sum0, 1);
        sum0 += __shfl_xor_sync(0xffffffffu, sum0, 2);
        sum1 += __shfl_xor_sync(0xffffffffu, sum1, 1);
        sum1 += __shfl_xor_sync(0xffffffffu, sum1, 2);
        l0 = l0 * sc0 + sum0; l1 = l1 * sc1 + sum1;
        m0s = nm0; m1s = nm1;
        #pragma unroll
        for (int nt = 0; nt < 8; nt++){
            O[nt][0] *= sc0; O[nt][1] *= sc0;
            O[nt][2] *= sc1; O[nt][3] *= sc1;
        }

        #pragma unroll
        for (int kc = 0; kc < 4; kc++){
            uint32_t ph[4];
            int ta = 2 * kc, tb = 2 * kc + 1;
            ph[0] = packh(S[ta][0], S[ta][1]);
            ph[1] = packh(S[ta][2], S[ta][3]);
            ph[2] = packh(S[tb][0], S[tb][1]);
            ph[3] = packh(S[tb][2], S[tb][3]);
            uint32_t vf[4][4];
            #pragma unroll
            for (int np = 0; np < 4; np++){
                int row = np * 16 + ((lane & 7) | ((lane >> 4) << 3));
                uint32_t col = kc * 32 + (((lane >> 3) & 1) << 4);
                ldm_x4(vs + row * VROWB + col, vf[np][0], vf[np][1], vf[np][2], vf[np][3]);
            }
            #pragma unroll
            for (int nt = 0; nt < 8; nt++)
                mma16816(O[nt], ph, &vf[nt >> 1][(nt & 1) * 2]);
        }
        __syncthreads();
    }

    // ---- write O as fp16 ----
    float inv0 = 1.0f / l0, inv1 = 1.0f / l1;
    int r0 = w * 16 + (lane >> 2);
    int col = (lane & 3) * 2;
    long long tok0 = (long long)b * 4096 + m0 + r0;
    #pragma unroll
    for (int nt = 0; nt < 8; nt++){
        int d = nt * 8 + col;
        __half2 v0 = __floats2half2_rn(O[nt][0] * inv0, O[nt][1] * inv0);
        __half2 v1 = __floats2half2_rn(O[nt][2] * inv1, O[nt][3] * inv1);
        *(__half2*)(oW + tok0 * 512 + h * 64 + d)       = v0;
        *(__half2*)(oW + (tok0 + 8) * 512 + h * 64 + d) = v1;
    }
}

// ============================ LayerNorm -> fp16 ============================
__global__ void ln_half(const float* __restrict__ x, const float* __restrict__ g,
                        const float* __restrict__ beta, __half* __restrict__ y){
    long long row = blockIdx.x;
    const float* xr = x + row * DIMC;
    int t = threadIdx.x;
    float a0 = xr[t], a1 = xr[t + 256];
    float s  = a0 + a1, ss = a0 * a0 + a1 * a1;
    #pragma unroll
    for (int o = 16; o > 0; o >>= 1){
        s  += __shfl_xor_sync(0xffffffffu, s,  o);
        ss += __shfl_xor_sync(0xffffffffu, ss, o);
    }
    __shared__ float s1[8], s2[8];
    if ((t & 31) == 0){ s1[t >> 5] = s; s2[t >> 5] = ss; }
    __syncthreads();
    float tot = 0.f, tot2 = 0.f;
    #pragma unroll
    for (int i = 0; i < 8; i++){ tot += s1[i]; tot2 += s2[i]; }
    float mu  = tot * (1.0f / DIMC);
    float var = tot2 * (1.0f / DIMC) - mu * mu;
    float rsv = rsqrtf(var + 1e-5f);
    __half* yr = y + row * DIMC;
    yr[t]       = __float2half((a0 - mu) * rsv * g[t]       + beta[t]);
    yr[t + 256] = __float2half((a1 - mu) * rsv * g[t + 256] + beta[t + 256]);
}

// ============================ weight transpose -> fp16 [N][K] ============================
__global__ void thalf(const float* __restrict__ W, __half* __restrict__ out, int K, int N){
    __shared__ float tile[32][33];
    int k0 = blockIdx.x * 32, n0 = blockIdx.y * 32;
    int tx = threadIdx.x, ty = threadIdx.y;
    #pragma unroll
    for (int j = 0; j < 4; j++)
        tile[ty + j * 8][tx] = W[(long long)(k0 + ty + j * 8) * N + n0 + tx];
    __syncthreads();
    #pragma unroll
    for (int j = 0; j < 4; j++){
        int n = n0 + ty + j * 8;
        out[(long long)n * K + k0 + tx] = __float2half(tile[tx][ty + j * 8]);
    }
}

// ============================ PE layer 1 -> fp16 ============================
__global__ void pe1_half(const float* __restrict__ pos, const float* __restrict__ w1,
                         const float* __restrict__ b1, __half* __restrict__ out){
    long long idx = (long long)blockIdx.x * 256 + threadIdx.x;   // 8192*512
    int m = (int)(idx >> 9), c = (int)(idx & 511);
    float p0 = pos[m * 3], p1 = pos[m * 3 + 1], p2 = pos[m * 3 + 2];
    float v = gelu_f(p0 * w1[c] + p1 * w1[512 + c] + p2 * w1[1024 + c] + b1[c]);
    out[idx] = __float2half(v);
}

// ============================ host ============================
extern "C" void kernel_launch(void* const* d_in, const int* in_sizes, int n_in,
                              void* d_out, int out_size){
    const float* x      = (const float*)d_in[0];
    const float* pos    = (const float*)d_in[1];
    const float* qkv_w  = (const float*)d_in[2];
    const float* qkv_b  = (const float*)d_in[3];
    const float* proj_w = (const float*)d_in[4];
    const float* proj_b = (const float*)d_in[5];
    const float* pe_w1  = (const float*)d_in[6];
    const float* pe_b1  = (const float*)d_in[7];
    const float* pe_w2  = (const float*)d_in[8];
    const float* pe_b2  = (const float*)d_in[9];
    const float* mlp_w1 = (const float*)d_in[10];
    const float* mlp_b1 = (const float*)d_in[11];
    const float* mlp_w2 = (const float*)d_in[12];
    const float* mlp_b2 = (const float*)d_in[13];
    const float* n1_g   = (const float*)d_in[14];
    const float* n1_b   = (const float*)d_in[15];
    const float* n2_g   = (const float*)d_in[16];
    const float* n2_b   = (const float*)d_in[17];
    float* out = (float*)d_out;

    __half *hW, *qA, *kW, *vT, *oW, *m1W;
    __half *qkvB, *pe2B, *projB, *mlp1B, *mlp2B;
    float *pef, *x2f;
    cudaGetSymbolAddress((void**)&hW,   g_hW);
    cudaGetSymbolAddress((void**)&pef,  g_pef);
    cudaGetSymbolAddress((void**)&qA,   g_qA);
    cudaGetSymbolAddress((void**)&kW,   g_kW);
    cudaGetSymbolAddress((void**)&vT,   g_vT);
    cudaGetSymbolAddress((void**)&oW,   g_oW);
    cudaGetSymbolAddress((void**)&x2f,  g_x2f);
    cudaGetSymbolAddress((void**)&m1W,  g_m1W);
    cudaGetSymbolAddress((void**)&qkvB, g_qkvB);
    cudaGetSymbolAddress((void**)&pe2B, g_pe2B);
    cudaGetSymbolAddress((void**)&projB,g_projB);
    cudaGetSymbolAddress((void**)&mlp1B,g_mlp1B);
    cudaGetSymbolAddress((void**)&mlp2B,g_mlp2B);

    __half* peW = m1W;   // disjoint lifetime

    cudaFuncSetAttribute(mmagemm,    cudaFuncAttributeMaxDynamicSharedMemorySize, DYN_SMEM);
    cudaFuncSetAttribute(qkv_gemm,   cudaFuncAttributeMaxDynamicSharedMemorySize, DYN_SMEM);
    cudaFuncSetAttribute(flash_attn, cudaFuncAttributeMaxDynamicSharedMemorySize, FA_SMEM);

    dim3 tsb(32, 8);

    // weight transposes to fp16
    thalf<<<dim3(512/32, 1536/32), tsb>>>(qkv_w,  qkvB, 512, 1536);
    thalf<<<dim3(512/32,  512/32), tsb>>>(pe_w2,  pe2B, 512, 512);
    thalf<<<dim3(512/32,  512/32), tsb>>>(proj_w, projB, 512, 512);
    thalf<<<dim3(512/32, 2048/32), tsb>>>(mlp_w1, mlp1B, 512, 2048);
    thalf<<<dim3(2048/32, 512/32), tsb>>>(mlp_w2, mlp2B, 2048, 512);

    // 1. peW = fp16(gelu(pos @ pe_w1 + pe_b1)); pe = peW @ pe2B^T + pe_b2
    pe1_half<<<(NTOK*DIMC)/256, 256>>>(pos, pe_w1, pe_b1, peW);
    mmagemm<<<dim3(4, 64, 1), 256, DYN_SMEM>>>(
        peW, pe2B, pe_b2, nullptr, pef, nullptr,
        512, 512, 512, 512, 0);

    // 2. hW = fp16(LN1(x))
    ln_half<<<NTOK, 256>>>(x, n1_g, n1_b, hW);

    // 3. qkv GEMM with fused operand construction
    qkv_gemm<<<dim3(12, 64, 1), 256, DYN_SMEM>>>(
        hW, qkvB, qkv_b, pef, qA, kW, vT);

    // 4. fused flash attention -> oW (fp16)
    flash_attn<<<dim3(32, 16), 256, FA_SMEM>>>(qA, kW, vT, oW);

    // 5. x2 = x + oW @ projB^T + proj_b
    mmagemm<<<dim3(4, 64, 1), 256, DYN_SMEM>>>(
        oW, projB, proj_b, x, x2f, nullptr,
        512, 512, 512, 512, 2);

    // 6. hW = fp16(LN2(x2))
    ln_half<<<NTOK, 256>>>(x2f, n2_g, n2_b, hW);

    // 7. m1W = fp16(gelu(hW @ mlp1B^T + mlp_b1))
    mmagemm<<<dim3(16, 64, 1), 256, DYN_SMEM>>>(
        hW, mlp1B, mlp_b1, nullptr, nullptr, m1W,
        512, 512, 512, 2048, 1);

    // 8. out = x2 + m1W @ mlp2B^T + mlp_b2
    mmagemm<<<dim3(4, 64, 1), 256, DYN_SMEM>>>(
        m1W, mlp2B, mlp_b2, x2f, out, nullptr,
        2048, 2048, 2048, 512, 2);
}

// round 11
// speedup vs baseline: 7.3160x; 1.0587x over previous
#include <cuda_runtime.h>
#include <cuda_fp16.h>
#include <math.h>
#include <stdint.h>

#define DIMC 512
#define NTOK 8192      // B*N
#define SEQ  4096
#define HEADS 8
#define MLPH 2048
#define BH   16

// ============================ scratch buffers ============================
__device__ __align__(256) __half g_hW  [8192ULL*512];    // ln out
__device__ __align__(256) __half g_peH [8192ULL*512];    // pe (fp16)
__device__ __align__(256) __half g_qA  [16ULL*4096*64];  // q (scale*log2e folded) [bh][n][d]
__device__ __align__(256) __half g_kW  [16ULL*4096*64];  // k [bh][n][d]
__device__ __align__(256) __half g_vT  [16ULL*64*4096];  // V transposed [bh][d][n]
__device__ __align__(256) __half g_oW  [8192ULL*512];    // attn out
__device__ __align__(256) float  g_x2f [8192ULL*512];
__device__ __align__(256) __half g_m1W [8192ULL*2048];   // mlp hidden; also hosts peW early
__device__ __align__(256) __half g_qkvB [1536ULL*512];   // weights transposed [N][K]
__device__ __align__(256) __half g_pe2B [512ULL*512];
__device__ __align__(256) __half g_projB[512ULL*512];
__device__ __align__(256) __half g_mlp1B[2048ULL*512];
__device__ __align__(256) __half g_mlp2B[512ULL*2048];

// ============================ helpers ============================
__device__ __forceinline__ uint32_t smem_u32(const void* p){
    uint32_t a;
    asm("{ .reg .u64 t; cvta.to.shared.u64 t, %1; cvt.u32.u64 %0, t; }" : "=r"(a) : "l"(p));
    return a;
}
__device__ __forceinline__ float gelu_f(float v){
    return 0.5f * v * (1.0f + erff(v * 0.70710678118654752440f));
}
__device__ __forceinline__ float fexp2(float x){
    float y;
    asm("ex2.approx.ftz.f32 %0, %1;" : "=f"(y) : "f"(x));
    return y;
}
__device__ __forceinline__ uint32_t packh(float a, float b){
    __half2 t = __floats2half2_rn(a, b);
    return *(uint32_t*)&t;
}
__device__ __forceinline__ void cpasync16(uint32_t dst, const void* src, bool pred){
    asm volatile("cp.async.cg.shared.global [%0], [%1], 16, %2;"
                 :: "r"(dst), "l"(src), "r"(pred ? 16 : 0) : "memory");
}
#define CP_COMMIT()  asm volatile("cp.async.commit_group;" ::: "memory")
#define CP_WAIT(n)   asm volatile("cp.async.wait_group %0;" :: "n"(n) : "memory")

__device__ __forceinline__ void ldm_x4(uint32_t addr, uint32_t& r0, uint32_t& r1,
                                       uint32_t& r2, uint32_t& r3){
    asm volatile("ldmatrix.sync.aligned.m8n8.x4.shared.b16 {%0,%1,%2,%3}, [%4];"
                 : "=r"(r0), "=r"(r1), "=r"(r2), "=r"(r3) : "r"(addr));
}
__device__ __forceinline__ void mma16816(float* c, const uint32_t* a, const uint32_t* b){
    asm volatile("mma.sync.aligned.m16n8k16.row.col.f32.f16.f16.f32 "
                 "{%0,%1,%2,%3}, {%4,%5,%6,%7}, {%8,%9}, {%0,%1,%2,%3};"
                 : "+f"(c[0]), "+f"(c[1]), "+f"(c[2]), "+f"(c[3])
                 : "r"(a[0]), "r"(a[1]), "r"(a[2]), "r"(a[3]), "r"(b[0]), "r"(b[1]));
}

// ============================ GEMM common ============================
#define ROWB 144                 // smem row stride bytes (64 fp16 + 8 pad)
#define TBUF (128 * ROWB)        // 18432 bytes per tile buffer
#define DYN_SMEM (4 * TBUF)      // 73728

__device__ __forceinline__ void load_tile(const __half* __restrict__ G, int ldE,
                                          uint32_t smbase, int tid){
    #pragma unroll
    for (int i = 0; i < 4; i++){
        int id  = tid + i * 256;          // 0..1023
        int r   = id >> 3, c16 = id & 7;
        const char* src = (const char*)(G + (long long)r * ldE) + c16 * 16;
        cpasync16(smbase + r * ROWB + c16 * 16, src, true);
    }
}

// 128x128 tile accumulate over K, BK=64, double buffered
__device__ __forceinline__ void gemm_mainloop(
    const __half* __restrict__ A, const __half* __restrict__ B,
    int Kp, int lda, int ldb, long long m0, long long n0,
    uint32_t smu, int tid, int lane, int wm, int wn, float acc[2][8][4])
{
    uint32_t asb[2] = { smu,        smu + 2 * TBUF };
    uint32_t bsb[2] = { smu + TBUF, smu + 3 * TBUF };
    int nc = Kp >> 6;
    load_tile(A + m0 * lda, lda, asb[0], tid);
    load_tile(B + n0 * ldb, ldb, bsb[0], tid);
    CP_COMMIT();

    for (int c = 0; c < nc; c++){
        int cur = c & 1;
        if (c + 1 < nc){
            load_tile(A + m0 * lda + (c + 1) * 64, lda, asb[cur ^ 1], tid);
            load_tile(B + n0 * ldb + (c + 1) * 64, ldb, bsb[cur ^ 1], tid);
            CP_COMMIT();
            CP_WAIT(1);
        } else {
            CP_WAIT(0);
        }
        __syncthreads();

        #pragma unroll
        for (int kk = 0; kk < 4; kk++){
            uint32_t afr[2][4], bfr[4][4];
            #pragma unroll
            for (int mt = 0; mt < 2; mt++){
                int row = wm + mt * 16 + (lane & 15);
                uint32_t addr = asb[cur] + row * ROWB + kk * 32 + ((lane >> 4) << 4);
                ldm_x4(addr, afr[mt][0], afr[mt][1], afr[mt][2], afr[mt][3]);
            }
            #pragma unroll
            for (int np = 0; np < 4; np++){
                int row = wn + np * 16 + ((lane & 7) | ((lane >> 4) << 3));
                uint32_t addr = bsb[cur] + row * ROWB + kk * 32 + (((lane >> 3) & 1) << 4);
                ldm_x4(addr, bfr[np][0], bfr[np][1], bfr[np][2], bfr[np][3]);
            }
            #pragma unroll
            for (int mt = 0; mt < 2; mt++)
                #pragma unroll
                for (int nt = 0; nt < 8; nt++)
                    mma16816(acc[mt][nt], afr[mt], &bfr[nt >> 1][(nt & 1) * 2]);
        }
        __syncthreads();
    }
}

// ============================ generic GEMM ============================
// C[M,Ntot] = A @ B^T (+bias)(gelu)(+res) -> fp32 C or fp16 Ch (both stride ldc).
__global__ void __launch_bounds__(256, 2) mmagemm(
    const __half* __restrict__ A, const __half* __restrict__ B,
    const float* __restrict__ bias, const float* __restrict__ res,
    float* __restrict__ C, __half* __restrict__ Ch,
    int Kp, int lda, int ldb, int ldc, int epi)
{
    extern __shared__ char dynsm[];
    int tid = threadIdx.x, lane = tid & 31, w = tid >> 5;
    int wm = (w & 3) * 32, wn = (w >> 2) * 64;
    long long m0 = blockIdx.y * 128;
    long long n0 = blockIdx.x * 128;
    uint32_t smu = smem_u32(dynsm);

    float acc[2][8][4];
    #pragma unroll
    for (int i = 0; i < 2; i++)
        #pragma unroll
        for (int j = 0; j < 8; j++)
            #pragma unroll
            for (int q = 0; q < 4; q++) acc[i][j][q] = 0.f;

    gemm_mainloop(A, B, Kp, lda, ldb, m0, n0, smu, tid, lane, wm, wn, acc);

    float* Cs = (float*)dynsm;   // 128 x 132
    #pragma unroll
    for (int mt = 0; mt < 2; mt++)
        #pragma unroll
        for (int nt = 0; nt < 8; nt++){
            int r  = wm + mt * 16 + (lane >> 2);
            int cc = wn + nt * 8 + (lane & 3) * 2;
            Cs[r * 132 + cc]           = acc[mt][nt][0];
            Cs[r * 132 + cc + 1]       = acc[mt][nt][1];
            Cs[(r + 8) * 132 + cc]     = acc[mt][nt][2];
            Cs[(r + 8) * 132 + cc + 1] = acc[mt][nt][3];
        }
    __syncthreads();

    for (int e = tid; e < 128 * 128; e += 256){
        int rr = e >> 7, cc = e & 127;
        int gc = (int)n0 + cc;
        float v = Cs[rr * 132 + cc];
        if (bias)     v += bias[gc];
        if (epi & 1)  v  = gelu_f(v);
        long long ga = (m0 + rr) * ldc + gc;
        if (Ch){
            Ch[ga] = __float2half(v);
        } else {
            if (epi & 2) v += res[ga];
            C[ga] = v;
        }
    }
}

// ============================ QKV GEMM with fused operand-build epilogue ============================
// qkv = hW @ qkvB^T + bias; q(+pe, *0.125*log2e)->qA, k(+pe)->kW, v->vT (transposed).
__global__ void __launch_bounds__(256, 2) qkv_gemm(
    const __half* __restrict__ A, const __half* __restrict__ B,
    const float* __restrict__ bias, const __half* __restrict__ pe,
    __half* __restrict__ qA, __half* __restrict__ kW, __half* __restrict__ vT)
{
    extern __shared__ char dynsm[];
    int tid = threadIdx.x, lane = tid & 31, w = tid >> 5;
    int wm = (w & 3) * 32, wn = (w >> 2) * 64;
    long long m0 = blockIdx.y * 128;
    long long n0 = blockIdx.x * 128;
    uint32_t smu = smem_u32(dynsm);

    float acc[2][8][4];
    #pragma unroll
    for (int i = 0; i < 2; i++)
        #pragma unroll
        for (int j = 0; j < 8; j++)
            #pragma unroll
            for (int q = 0; q < 4; q++) acc[i][j][q] = 0.f;

    gemm_mainloop(A, B, 512, 512, 512, m0, n0, smu, tid, lane, wm, wn, acc);

    float* Cs = (float*)dynsm;   // 128 x 129 (odd stride: conflict-free col reads)
    #pragma unroll
    for (int mt = 0; mt < 2; mt++)
        #pragma unroll
        for (int nt = 0; nt < 8; nt++){
            int r  = wm + mt * 16 + (lane >> 2);
            int cc = wn + nt * 8 + (lane & 3) * 2;
            Cs[r * 129 + cc]           = acc[mt][nt][0];
            Cs[r * 129 + cc + 1]       = acc[mt][nt][1];
            Cs[(r + 8) * 129 + cc]     = acc[mt][nt][2];
            Cs[(r + 8) * 129 + cc + 1] = acc[mt][nt][3];
        }
    __syncthreads();

    int gtype = (int)(n0 >> 9);   // 0 q, 1 k, 2 v
    if (gtype < 2){
        for (int e = tid; e < 128 * 128; e += 256){
            int rr = e >> 7, cc = e & 127;
            int token = (int)m0 + rr;
            int c = ((int)n0 & 511) + cc;
            float val = Cs[rr * 129 + cc] + bias[(int)n0 + cc]
                      + __half2float(pe[(long long)token * 512 + c]);
            int bq = token >> 12, n = token & 4095;
            int h = c >> 6, d = c & 63;
            long long r = ((long long)(bq * 8 + h) * 4096 + n) * 64 + d;
            if (gtype == 0) qA[r] = __float2half(val * 0.18033688011f);  // 0.125*log2(e)
            else            kW[r] = __float2half(val);
        }
    } else {
        for (int e = tid; e < 128 * 128; e += 256){
            int dl = e >> 7, rr = e & 127;          // column-major: coalesced n writes
            int token = (int)m0 + rr;
            int c = ((int)n0 & 511) + dl;
            float val = Cs[rr * 129 + dl] + bias[(int)n0 + dl];
            int bq = token >> 12, n = token & 4095;
            int h = c >> 6, d = c & 63;
            vT[((long long)(bq * 8 + h) * 64 + d) * 4096 + n] = __float2half(val);
        }
    }
}

// ============================ flash attention (base-2 softmax, non-persistent) ============================
#define QROWB 144
#define KROWB 144
#define VROWB 144
#define FA_QS   0
#define FA_KS   18432                       // + buf*9216
#define FA_VS   (18432 + 2*9216)            // + buf*9216
#define FA_SMEM (FA_VS + 2*9216)            // 55296

__device__ __forceinline__ void fa_load_kv(
    const __half* __restrict__ kW, const __half* __restrict__ vT,
    long long kbase, long long vbase, int c, uint32_t smu, int buf, int tid)
{
    uint32_t ks = smu + FA_KS + buf * 9216;
    uint32_t vs = smu + FA_VS + buf * 9216;
    #pragma unroll
    for (int i = 0; i < 2; i++){            // K: 64 rows x 128B
        int id = tid + i * 256;
        int r = id >> 3, c16 = id & 7;
        cpasync16(ks + r * KROWB + c16 * 16,
                  kW + kbase + (long long)(c * 64 + r) * 64 + c16 * 8, true);
    }
    #pragma unroll
    for (int i = 0; i < 2; i++){            // V^T: 64 d-rows x 128B
        int id = tid + i * 256;
        int r = id >> 3, c16 = id & 7;
        cpasync16(vs + r * VROWB + c16 * 16,
                  vT + vbase + (long long)r * 4096 + c * 64 + c16 * 8, true);
    }
}

__global__ void __launch_bounds__(256, 2) flash_attn(
    const __half* __restrict__ qA, const __half* __restrict__ kW,
    const __half* __restrict__ vT, __half* __restrict__ oW)
{
    extern __shared__ char dynsm[];
    uint32_t smu = smem_u32(dynsm);
    int tid = threadIdx.x, lane = tid & 31, w = tid >> 5;
    int bh = blockIdx.y;
    int b = bh >> 3, h = bh & 7;
    int m0 = blockIdx.x * 128;

    long long qbase = ((long long)bh * 4096 + m0) * 64;
    long long kbase = (long long)bh * 4096 * 64;
    long long vbase = (long long)bh * 64 * 4096;

    #pragma unroll
    for (int i = 0; i < 4; i++){            // Q: 128 rows x 128B
        int id = tid + i * 256;
        int r = id >> 3, c16 = id & 7;
        cpasync16(smu + FA_QS + r * QROWB + c16 * 16,
                  qA + qbase + (long long)r * 64 + c16 * 8, true);
    }
    CP_COMMIT();
    fa_load_kv(kW, vT, kbase, vbase, 0, smu, 0, tid);
    CP_COMMIT();
    CP_WAIT(1);
    __syncthreads();

    uint32_t qf[4][4];
    #pragma unroll
    for (int kk = 0; kk < 4; kk++){
        int row = w * 16 + (lane & 15);
        uint32_t addr = smu + FA_QS + row * QROWB + kk * 32 + ((lane >> 4) << 4);
        ldm_x4(addr, qf[kk][0], qf[kk][1], qf[kk][2], qf[kk][3]);
    }

    float O[8][4];
    #pragma unroll
    for (int i = 0; i < 8; i++)
        #pragma unroll
        for (int j = 0; j < 4; j++) O[i][j] = 0.f;
    float m0s = -1e30f, m1s = -1e30f, l0 = 0.f, l1 = 0.f;

    for (int c = 0; c < 64; c++){
        int buf = c & 1;
        if (c + 1 < 64){
            fa_load_kv(kW, vT, kbase, vbase, c + 1, smu, buf ^ 1, tid);
            CP_COMMIT();
            CP_WAIT(1);
        } else {
            CP_WAIT(0);
        }
        __syncthreads();

        uint32_t ks = smu + FA_KS + buf * 9216;
        uint32_t vs = smu + FA_VS + buf * 9216;

        float S[8][4];
        #pragma unroll
        for (int i = 0; i < 8; i++)
            #pragma unroll
            for (int j = 0; j < 4; j++) S[i][j] = 0.f;
        #pragma unroll
        for (int kk = 0; kk < 4; kk++){
            uint32_t bfr[4][4];
            #pragma unroll
            for (int np = 0; np < 4; np++){
                int row = np * 16 + ((lane & 7) | ((lane >> 4) << 3));
                uint32_t addr = ks + row * KROWB + kk * 32 + (((lane >> 3) & 1) << 4);
                ldm_x4(addr, bfr[np][0], bfr[np][1], bfr[np][2], bfr[np][3]);
            }
            #pragma unroll
            for (int nt = 0; nt < 8; nt++)
                mma16816(S[nt], qf[kk], &bfr[nt >> 1][(nt & 1) * 2]);
        }

        // S holds logits * log2(e) -> base-2 online softmax (exactly equivalent)
        float mx0 = -1e30f, mx1 = -1e30f;
        #pragma unroll
        for (int nt = 0; nt < 8; nt++){
            mx0 = fmaxf(mx0, fmaxf(S[nt][0], S[nt][1]));
            mx1 = fmaxf(mx1, fmaxf(S[nt][2], S[nt][3]));
        }
        mx0 = fmaxf(mx0, __shfl_xor_sync(0xffffffffu, mx0, 1));
        mx0 = fmaxf(mx0, __shfl_xor_sync(0xffffffffu, mx0, 2));
        mx1 = fmaxf(mx1, __shfl_xor_sync(0xffffffffu, mx1, 1));
        mx1 = fmaxf(mx1, __shfl_xor_sync(0xffffffffu, mx1, 2));
        float nm0 = fmaxf(m0s, mx0), nm1 = fmaxf(m1s, mx1);
        float sc0 = fexp2(m0s - nm0), sc1 = fexp2(m1s - nm1);
        float sum0 = 0.f, sum1 = 0.f;
        #pragma unroll
        for (int nt = 0; nt < 8; nt++){
            S[nt][0] = fexp2(S[nt][0] - nm0); sum0 += S[nt][0];
            S[nt][1] = fexp2(S[nt][1] - nm0); sum0 += S[nt][1];
            S[nt][2] = fexp2(S[nt][2] - nm1); sum1 += S[nt][2];
            S[nt][3] = fexp2(S[nt][3] - nm1); sum1 += S[nt][3];
        }
        sum0 += __shfl_xor_sync(0xffffffffu, sum0, 1);
        sum0 += __shfl_xor_sync(0xffffffffu, sum0, 2);
        sum1 += __shfl_xor_sync(0xffffffffu, sum1, 1);
        sum1 += __shfl_xor_sync(0xffffffffu, sum1, 2);
        l0 = l0 * sc0 + sum0; l1 = l1 * sc1 + sum1;
        m0s = nm0; m1s = nm1;
        #pragma unroll
        for (int nt = 0; nt < 8; nt++){
            O[nt][0] *= sc0; O[nt][1] *= sc0;
            O[nt][2] *= sc1; O[nt][3] *= sc1;
        }

        #pragma unroll
        for (int kc = 0; kc < 4; kc++){
            uint32_t ph[4];
            int ta = 2 * kc, tb = 2 * kc + 1;
            ph[0] = packh(S[ta][0], S[ta][1]);
            ph[1] = packh(S[ta][2], S[ta][3]);
            ph[2] = packh(S[tb][0], S[tb][1]);
            ph[3] = packh(S[tb][2], S[tb][3]);
            uint32_t vf[4][4];
            #pragma unroll
            for (int np = 0; np < 4; np++){
                int row = np * 16 + ((lane & 7) | ((lane >> 4) << 3));
                uint32_t col = kc * 32 + (((lane >> 3) & 1) << 4);
                ldm_x4(vs + row * VROWB + col, vf[np][0], vf[np][1], vf[np][2], vf[np][3]);
            }
            #pragma unroll
            for (int nt = 0; nt < 8; nt++)
                mma16816(O[nt], ph, &vf[nt >> 1][(nt & 1) * 2]);
        }
        __syncthreads();
    }

    // ---- write O as fp16 ----
    float inv0 = 1.0f / l0, inv1 = 1.0f / l1;
    int r0 = w * 16 + (lane >> 2);
    int col = (lane & 3) * 2;
    long long tok0 = (long long)b * 4096 + m0 + r0;
    #pragma unroll
    for (int nt = 0; nt < 8; nt++){
        int d = nt * 8 + col;
        __half2 v0 = __floats2half2_rn(O[nt][0] * inv0, O[nt][1] * inv0);
        __half2 v1 = __floats2half2_rn(O[nt][2] * inv1, O[nt][3] * inv1);
        *(__half2*)(oW + tok0 * 512 + h * 64 + d)       = v0;
        *(__half2*)(oW + (tok0 + 8) * 512 + h * 64 + d) = v1;
    }
}

// ============================ LayerNorm -> fp16 ============================
__global__ void ln_half(const float* __restrict__ x, const float* __restrict__ g,
                        const float* __restrict__ beta, __half* __restrict__ y){
    long long row = blockIdx.x;
    const float* xr = x + row * DIMC;
    int t = threadIdx.x;
    float a0 = xr[t], a1 = xr[t + 256];
    float s  = a0 + a1, ss = a0 * a0 + a1 * a1;
    #pragma unroll
    for (int o = 16; o > 0; o >>= 1){
        s  += __shfl_xor_sync(0xffffffffu, s,  o);
        ss += __shfl_xor_sync(0xffffffffu, ss, o);
    }
    __shared__ float s1[8], s2[8];
    if ((t & 31) == 0){ s1[t >> 5] = s; s2[t >> 5] = ss; }
    __syncthreads();
    float tot = 0.f, tot2 = 0.f;
    #pragma unroll
    for (int i = 0; i < 8; i++){ tot += s1[i]; tot2 += s2[i]; }
    float mu  = tot * (1.0f / DIMC);
    float var = tot2 * (1.0f / DIMC) - mu * mu;
    float rsv = rsqrtf(var + 1e-5f);
    __half* yr = y + row * DIMC;
    yr[t]       = __float2half((a0 - mu) * rsv * g[t]       + beta[t]);
    yr[t + 256] = __float2half((a1 - mu) * rsv * g[t + 256] + beta[t + 256]);
}

// ============================ merged weight transpose -> fp16 [N][K] ============================
// Segments (32x32 tiles): qkv 768 | pe2 256 | proj 256 | mlp1 1024 | mlp2 1024 = 3328
__global__ void thalf_all(const float* __restrict__ W0, const float* __restrict__ W1,
                          const float* __restrict__ W2, const float* __restrict__ W3,
                          const float* __restrict__ W4,
                          __half* __restrict__ O0, __half* __restrict__ O1,
                          __half* __restrict__ O2, __half* __restrict__ O3,
                          __half* __restrict__ O4){
    __shared__ float tile[32][33];
    int t = blockIdx.x;
    const float* W; __half* O; int K, N, base;
    if      (t <  768){ W = W0; O = O0; K = 512;  N = 1536; base = 0;    }
    else if (t < 1024){ W = W1; O = O1; K = 512;  N = 512;  base = 768;  }
    else if (t < 1280){ W = W2; O = O2; K = 512;  N = 512;  base = 1024; }
    else if (t < 2304){ W = W3; O = O3; K = 512;  N = 2048; base = 1280; }
    else              { W = W4; O = O4; K = 2048; N = 512;  base = 2304; }
    int lt = t - base;
    int nx = N >> 5;
    int k0 = (lt / nx) * 32, n0 = (lt % nx) * 32;
    int tx = threadIdx.x, ty = threadIdx.y;
    #pragma unroll
    for (int j = 0; j < 4; j++)
        tile[ty + j * 8][tx] = W[(long long)(k0 + ty + j * 8) * N + n0 + tx];
    __syncthreads();
    #pragma unroll
    for (int j = 0; j < 4; j++){
        int n = n0 + ty + j * 8;
        O[(long long)n * K + k0 + tx] = __float2half(tile[tx][ty + j * 8]);
    }
}

// ============================ PE layer 1 -> fp16 ============================
__global__ void pe1_half(const float* __restrict__ pos, const float* __restrict__ w1,
                         const float* __restrict__ b1, __half* __restrict__ out){
    long long idx = (long long)blockIdx.x * 256 + threadIdx.x;   // 8192*512
    int m = (int)(idx >> 9), c = (int)(idx & 511);
    float p0 = pos[m * 3], p1 = pos[m * 3 + 1], p2 = pos[m * 3 + 2];
    float v = gelu_f(p0 * w1[c] + p1 * w1[512 + c] + p2 * w1[1024 + c] + b1[c]);
    out[idx] = __float2half(v);
}

// ============================ host ============================
extern "C" void kernel_launch(void* const* d_in, const int* in_sizes, int n_in,
                              void* d_out, int out_size){
    const float* x      = (const float*)d_in[0];
    const float* pos    = (const float*)d_in[1];
    const float* qkv_w  = (const float*)d_in[2];
    const float* qkv_b  = (const float*)d_in[3];
    const float* proj_w = (const float*)d_in[4];
    const float* proj_b = (const float*)d_in[5];
    const float* pe_w1  = (const float*)d_in[6];
    const float* pe_b1  = (const float*)d_in[7];
    const float* pe_w2  = (const float*)d_in[8];
    const float* pe_b2  = (const float*)d_in[9];
    const float* mlp_w1 = (const float*)d_in[10];
    const float* mlp_b1 = (const float*)d_in[11];
    const float* mlp_w2 = (const float*)d_in[12];
    const float* mlp_b2 = (const float*)d_in[13];
    const float* n1_g   = (const float*)d_in[14];
    const float* n1_b   = (const float*)d_in[15];
    const float* n2_g   = (const float*)d_in[16];
    const float* n2_b   = (const float*)d_in[17];
    float* out = (float*)d_out;

    __half *hW, *peH, *qA, *kW, *vT, *oW, *m1W;
    __half *qkvB, *pe2B, *projB, *mlp1B, *mlp2B;
    float *x2f;
    cudaGetSymbolAddress((void**)&hW,   g_hW);
    cudaGetSymbolAddress((void**)&peH,  g_peH);
    cudaGetSymbolAddress((void**)&qA,   g_qA);
    cudaGetSymbolAddress((void**)&kW,   g_kW);
    cudaGetSymbolAddress((void**)&vT,   g_vT);
    cudaGetSymbolAddress((void**)&oW,   g_oW);
    cudaGetSymbolAddress((void**)&x2f,  g_x2f);
    cudaGetSymbolAddress((void**)&m1W,  g_m1W);
    cudaGetSymbolAddress((void**)&qkvB, g_qkvB);
    cudaGetSymbolAddress((void**)&pe2B, g_pe2B);
    cudaGetSymbolAddress((void**)&projB,g_projB);
    cudaGetSymbolAddress((void**)&mlp1B,g_mlp1B);
    cudaGetSymbolAddress((void**)&mlp2B,g_mlp2B);

    __half* peW = m1W;   // disjoint lifetime

    cudaFuncSetAttribute(mmagemm,    cudaFuncAttributeMaxDynamicSharedMemorySize, DYN_SMEM);
    cudaFuncSetAttribute(qkv_gemm,   cudaFuncAttributeMaxDynamicSharedMemorySize, DYN_SMEM);
    cudaFuncSetAttribute(flash_attn, cudaFuncAttributeMaxDynamicSharedMemorySize, FA_SMEM);

    dim3 tsb(32, 8);

    // all weight transposes in one launch
    thalf_all<<<3328, tsb>>>(qkv_w, pe_w2, proj_w, mlp_w1, mlp_w2,
                             qkvB, pe2B, projB, mlp1B, mlp2B);

    // 1. peW = fp16(gelu(pos @ pe_w1 + pe_b1)); peH = fp16(peW @ pe2B^T + pe_b2)
    pe1_half<<<(NTOK*DIMC)/256, 256>>>(pos, pe_w1, pe_b1, peW);
    mmagemm<<<dim3(4, 64, 1), 256, DYN_SMEM>>>(
        peW, pe2B, pe_b2, nullptr, nullptr, peH,
        512, 512, 512, 512, 0);

    // 2. hW = fp16(LN1(x))
    ln_half<<<NTOK, 256>>>(x, n1_g, n1_b, hW);

    // 3. qkv GEMM with fused operand construction
    qkv_gemm<<<dim3(12, 64, 1), 256, DYN_SMEM>>>(
        hW, qkvB, qkv_b, peH, qA, kW, vT);

    // 4. fused flash attention -> oW (fp16)
    flash_attn<<<dim3(32, 16), 256, FA_SMEM>>>(qA, kW, vT, oW);

    // 5. x2 = x + oW @ projB^T + proj_b
    mmagemm<<<dim3(4, 64, 1), 256, DYN_SMEM>>>(
        oW, projB, proj_b, x, x2f, nullptr,
        512, 512, 512, 512, 2);

    // 6. hW = fp16(LN2(x2))
    ln_half<<<NTOK, 256>>>(x2f, n2_g, n2_b, hW);

    // 7. m1W = fp16(gelu(hW @ mlp1B^T + mlp_b1))
    mmagemm<<<dim3(16, 64, 1), 256, DYN_SMEM>>>(
        hW, mlp1B, mlp_b1, nullptr, nullptr, m1W,
        512, 512, 512, 2048, 1);

    // 8. out = x2 + m1W @ mlp2B^T + mlp_b2
    mmagemm<<<dim3(4, 64, 1), 256, DYN_SMEM>>>(
        m1W, mlp2B, mlp_b2, x2f, out, nullptr,
        2048, 2048, 2048, 512, 2);
}

// round 13
// speedup vs baseline: 7.4385x; 1.0167x over previous
#include <cuda_runtime.h>
#include <cuda_fp16.h>
#include <math.h>
#include <stdint.h>

#define DIMC 512
#define NTOK 8192      // B*N
#define SEQ  4096
#define HEADS 8
#define MLPH 2048
#define BH   16

// ============================ scratch buffers ============================
__device__ __align__(256) __half g_hW  [8192ULL*512];    // ln out
__device__ __align__(256) __half g_peH [8192ULL*512];    // pe (fp16)
__device__ __align__(256) __half g_qA  [16ULL*4096*64];  // q (scale*log2e folded) [bh][n][d]
__device__ __align__(256) __half g_kW  [16ULL*4096*64];  // k [bh][n][d]
__device__ __align__(256) __half g_vT  [16ULL*64*4096];  // V transposed [bh][d][n]
__device__ __align__(256) __half g_oW  [8192ULL*512];    // attn out
__device__ __align__(256) float  g_x2f [8192ULL*512];
__device__ __align__(256) __half g_m1W [8192ULL*2048];   // mlp hidden; also hosts peW early
__device__ __align__(256) __half g_qkvB [1536ULL*512];   // weights transposed [N][K]
__device__ __align__(256) __half g_pe2B [512ULL*512];
__device__ __align__(256) __half g_projB[512ULL*512];
__device__ __align__(256) __half g_mlp1B[2048ULL*512];
__device__ __align__(256) __half g_mlp2B[512ULL*2048];

// ============================ helpers ============================
__device__ __forceinline__ uint32_t smem_u32(const void* p){
    uint32_t a;
    asm("{ .reg .u64 t; cvta.to.shared.u64 t, %1; cvt.u32.u64 %0, t; }" : "=r"(a) : "l"(p));
    return a;
}
__device__ __forceinline__ float gelu_f(float v){
    return 0.5f * v * (1.0f + erff(v * 0.70710678118654752440f));
}
__device__ __forceinline__ float fexp2(float x){
    float y;
    asm("ex2.approx.ftz.f32 %0, %1;" : "=f"(y) : "f"(x));
    return y;
}
__device__ __forceinline__ uint32_t packh(float a, float b){
    __half2 t = __floats2half2_rn(a, b);
    return *(uint32_t*)&t;
}
__device__ __forceinline__ void cpasync16(uint32_t dst, const void* src, bool pred){
    asm volatile("cp.async.cg.shared.global [%0], [%1], 16, %2;"
                 :: "r"(dst), "l"(src), "r"(pred ? 16 : 0) : "memory");
}
#define CP_COMMIT()  asm volatile("cp.async.commit_group;" ::: "memory")
#define CP_WAIT(n)   asm volatile("cp.async.wait_group %0;" :: "n"(n) : "memory")

__device__ __forceinline__ void ldm_x4(uint32_t addr, uint32_t& r0, uint32_t& r1,
                                       uint32_t& r2, uint32_t& r3){
    asm volatile("ldmatrix.sync.aligned.m8n8.x4.shared.b16 {%0,%1,%2,%3}, [%4];"
                 : "=r"(r0), "=r"(r1), "=r"(r2), "=r"(r3) : "r"(addr));
}
__device__ __forceinline__ void mma16816(float* c, const uint32_t* a, const uint32_t* b){
    asm volatile("mma.sync.aligned.m16n8k16.row.col.f32.f16.f16.f32 "
                 "{%0,%1,%2,%3}, {%4,%5,%6,%7}, {%8,%9}, {%0,%1,%2,%3};"
                 : "+f"(c[0]), "+f"(c[1]), "+f"(c[2]), "+f"(c[3])
                 : "r"(a[0]), "r"(a[1]), "r"(a[2]), "r"(a[3]), "r"(b[0]), "r"(b[1]));
}

// ============================ GEMM common ============================
#define ROWB 144                 // smem row stride bytes (64 fp16 + 8 pad)
#define TBUF (128 * ROWB)        // 18432 bytes per tile buffer
#define DYN_SMEM (4 * TBUF)      // 73728

__device__ __forceinline__ void load_tile(const __half* __restrict__ G, int ldE,
                                          uint32_t smbase, int tid){
    #pragma unroll
    for (int i = 0; i < 4; i++){
        int id  = tid + i * 256;          // 0..1023
        int r   = id >> 3, c16 = id & 7;
        const char* src = (const char*)(G + (long long)r * ldE) + c16 * 16;
        cpasync16(smbase + r * ROWB + c16 * 16, src, true);
    }
}

// 128x128 tile accumulate over K, BK=64, double buffered
__device__ __forceinline__ void gemm_mainloop(
    const __half* __restrict__ A, const __half* __restrict__ B,
    int Kp, int lda, int ldb, long long m0, long long n0,
    uint32_t smu, int tid, int lane, int wm, int wn, float acc[2][8][4])
{
    uint32_t asb[2] = { smu,        smu + 2 * TBUF };
    uint32_t bsb[2] = { smu + TBUF, smu + 3 * TBUF };
    int nc = Kp >> 6;
    load_tile(A + m0 * lda, lda, asb[0], tid);
    load_tile(B + n0 * ldb, ldb, bsb[0], tid);
    CP_COMMIT();

    for (int c = 0; c < nc; c++){
        int cur = c & 1;
        if (c + 1 < nc){
            load_tile(A + m0 * lda + (c + 1) * 64, lda, asb[cur ^ 1], tid);
            load_tile(B + n0 * ldb + (c + 1) * 64, ldb, bsb[cur ^ 1], tid);
            CP_COMMIT();
            CP_WAIT(1);
        } else {
            CP_WAIT(0);
        }
        __syncthreads();

        #pragma unroll
        for (int kk = 0; kk < 4; kk++){
            uint32_t afr[2][4], bfr[4][4];
            #pragma unroll
            for (int mt = 0; mt < 2; mt++){
                int row = wm + mt * 16 + (lane & 15);
                uint32_t addr = asb[cur] + row * ROWB + kk * 32 + ((lane >> 4) << 4);
                ldm_x4(addr, afr[mt][0], afr[mt][1], afr[mt][2], afr[mt][3]);
            }
            #pragma unroll
            for (int np = 0; np < 4; np++){
                int row = wn + np * 16 + ((lane & 7) | ((lane >> 4) << 3));
                uint32_t addr = bsb[cur] + row * ROWB + kk * 32 + (((lane >> 3) & 1) << 4);
                ldm_x4(addr, bfr[np][0], bfr[np][1], bfr[np][2], bfr[np][3]);
            }
            #pragma unroll
            for (int mt = 0; mt < 2; mt++)
                #pragma unroll
                for (int nt = 0; nt < 8; nt++)
                    mma16816(acc[mt][nt], afr[mt], &bfr[nt >> 1][(nt & 1) * 2]);
        }
        __syncthreads();
    }
}

// ============================ generic GEMM ============================
// C[M,Ntot] = A @ B^T (+bias)(gelu)(+res) -> fp32 C or fp16 Ch (both stride ldc).
__global__ void __launch_bounds__(256, 2) mmagemm(
    const __half* __restrict__ A, const __half* __restrict__ B,
    const float* __restrict__ bias, const float* __restrict__ res,
    float* __restrict__ C, __half* __restrict__ Ch,
    int Kp, int lda, int ldb, int ldc, int epi)
{
    extern __shared__ char dynsm[];
    int tid = threadIdx.x, lane = tid & 31, w = tid >> 5;
    int wm = (w & 3) * 32, wn = (w >> 2) * 64;
    long long m0 = blockIdx.y * 128;
    long long n0 = blockIdx.x * 128;
    uint32_t smu = smem_u32(dynsm);

    float acc[2][8][4];
    #pragma unroll
    for (int i = 0; i < 2; i++)
        #pragma unroll
        for (int j = 0; j < 8; j++)
            #pragma unroll
            for (int q = 0; q < 4; q++) acc[i][j][q] = 0.f;

    gemm_mainloop(A, B, Kp, lda, ldb, m0, n0, smu, tid, lane, wm, wn, acc);

    float* Cs = (float*)dynsm;   // 128 x 132
    #pragma unroll
    for (int mt = 0; mt < 2; mt++)
        #pragma unroll
        for (int nt = 0; nt < 8; nt++){
            int r  = wm + mt * 16 + (lane >> 2);
            int cc = wn + nt * 8 + (lane & 3) * 2;
            Cs[r * 132 + cc]           = acc[mt][nt][0];
            Cs[r * 132 + cc + 1]       = acc[mt][nt][1];
            Cs[(r + 8) * 132 + cc]     = acc[mt][nt][2];
            Cs[(r + 8) * 132 + cc + 1] = acc[mt][nt][3];
        }
    __syncthreads();

    for (int e = tid; e < 128 * 128; e += 256){
        int rr = e >> 7, cc = e & 127;
        int gc = (int)n0 + cc;
        float v = Cs[rr * 132 + cc];
        if (bias)     v += bias[gc];
        if (epi & 1)  v  = gelu_f(v);
        long long ga = (m0 + rr) * ldc + gc;
        if (Ch){
            Ch[ga] = __float2half(v);
        } else {
            if (epi & 2) v += res[ga];
            C[ga] = v;
        }
    }
}

// ============================ QKV GEMM with fused operand-build epilogue ============================
// qkv = hW @ qkvB^T + bias; q(+pe, *0.125*log2e)->qA, k(+pe)->kW, v->vT (transposed).
__global__ void __launch_bounds__(256, 2) qkv_gemm(
    const __half* __restrict__ A, const __half* __restrict__ B,
    const float* __restrict__ bias, const __half* __restrict__ pe,
    __half* __restrict__ qA, __half* __restrict__ kW, __half* __restrict__ vT)
{
    extern __shared__ char dynsm[];
    int tid = threadIdx.x, lane = tid & 31, w = tid >> 5;
    int wm = (w & 3) * 32, wn = (w >> 2) * 64;
    long long m0 = blockIdx.y * 128;
    long long n0 = blockIdx.x * 128;
    uint32_t smu = smem_u32(dynsm);

    float acc[2][8][4];
    #pragma unroll
    for (int i = 0; i < 2; i++)
        #pragma unroll
        for (int j = 0; j < 8; j++)
            #pragma unroll
            for (int q = 0; q < 4; q++) acc[i][j][q] = 0.f;

    gemm_mainloop(A, B, 512, 512, 512, m0, n0, smu, tid, lane, wm, wn, acc);

    float* Cs = (float*)dynsm;   // 128 x 129 (odd stride: conflict-free col reads)
    #pragma unroll
    for (int mt = 0; mt < 2; mt++)
        #pragma unroll
        for (int nt = 0; nt < 8; nt++){
            int r  = wm + mt * 16 + (lane >> 2);
            int cc = wn + nt * 8 + (lane & 3) * 2;
            Cs[r * 129 + cc]           = acc[mt][nt][0];
            Cs[r * 129 + cc + 1]       = acc[mt][nt][1];
            Cs[(r + 8) * 129 + cc]     = acc[mt][nt][2];
            Cs[(r + 8) * 129 + cc + 1] = acc[mt][nt][3];
        }
    __syncthreads();

    int gtype = (int)(n0 >> 9);   // 0 q, 1 k, 2 v
    if (gtype < 2){
        for (int e = tid; e < 128 * 128; e += 256){
            int rr = e >> 7, cc = e & 127;
            int token = (int)m0 + rr;
            int c = ((int)n0 & 511) + cc;
            float val = Cs[rr * 129 + cc] + bias[(int)n0 + cc]
                      + __half2float(pe[(long long)token * 512 + c]);
            int bq = token >> 12, n = token & 4095;
            int h = c >> 6, d = c & 63;
            long long r = ((long long)(bq * 8 + h) * 4096 + n) * 64 + d;
            if (gtype == 0) qA[r] = __float2half(val * 0.18033688011f);  // 0.125*log2(e)
            else            kW[r] = __float2half(val);
        }
    } else {
        for (int e = tid; e < 128 * 128; e += 256){
            int dl = e >> 7, rr = e & 127;          // column-major: coalesced n writes
            int token = (int)m0 + rr;
            int c = ((int)n0 & 511) + dl;
            float val = Cs[rr * 129 + dl] + bias[(int)n0 + dl];
            int bq = token >> 12, n = token & 4095;
            int h = c >> 6, d = c & 63;
            vT[((long long)(bq * 8 + h) * 64 + d) * 4096 + n] = __float2half(val);
        }
    }
}

// ============================ flash attention (base-2 softmax, depth-3 KV pipeline) ============================
#define QROWB 144
#define KROWB 144
#define VROWB 144
#define FA_QS   0
#define FA_KV   18432                       // + stage*18432 (K at +0, V at +9216)
#define FA_SMEM (18432 + 3*18432)           // 73728

__device__ __forceinline__ void fa_load_kv(
    const __half* __restrict__ kW, const __half* __restrict__ vT,
    long long kbase, long long vbase, int c, uint32_t smu, int stage, int tid)
{
    uint32_t ks = smu + FA_KV + stage * 18432;
    uint32_t vs = ks + 9216;
    #pragma unroll
    for (int i = 0; i < 2; i++){            // K: 64 rows x 128B
        int id = tid + i * 256;
        int r = id >> 3, c16 = id & 7;
        cpasync16(ks + r * KROWB + c16 * 16,
                  kW + kbase + (long long)(c * 64 + r) * 64 + c16 * 8, true);
    }
    #pragma unroll
    for (int i = 0; i < 2; i++){            // V^T: 64 d-rows x 128B
        int id = tid + i * 256;
        int r = id >> 3, c16 = id & 7;
        cpasync16(vs + r * VROWB + c16 * 16,
                  vT + vbase + (long long)r * 4096 + c * 64 + c16 * 8, true);
    }
}

__global__ void __launch_bounds__(256, 2) flash_attn(
    const __half* __restrict__ qA, const __half* __restrict__ kW,
    const __half* __restrict__ vT, __half* __restrict__ oW)
{
    extern __shared__ char dynsm[];
    uint32_t smu = smem_u32(dynsm);
    int tid = threadIdx.x, lane = tid & 31, w = tid >> 5;
    int bh = blockIdx.y;
    int b = bh >> 3, h = bh & 7;
    int m0 = blockIdx.x * 128;

    long long qbase = ((long long)bh * 4096 + m0) * 64;
    long long kbase = (long long)bh * 4096 * 64;
    long long vbase = (long long)bh * 64 * 4096;

    #pragma unroll
    for (int i = 0; i < 4; i++){            // Q: 128 rows x 128B (group 1)
        int id = tid + i * 256;
        int r = id >> 3, c16 = id & 7;
        cpasync16(smu + FA_QS + r * QROWB + c16 * 16,
                  qA + qbase + (long long)r * 64 + c16 * 8, true);
    }
    CP_COMMIT();
    fa_load_kv(kW, vT, kbase, vbase, 0, smu, 0, tid);   // group 2
    CP_COMMIT();
    fa_load_kv(kW, vT, kbase, vbase, 1, smu, 1, tid);   // group 3
    CP_COMMIT();
    CP_WAIT(2);                             // Q arrived
    __syncthreads();                        // Q visible to all threads

    uint32_t qf[4][4];
    #pragma unroll
    for (int kk = 0; kk < 4; kk++){
        int row = w * 16 + (lane & 15);
        uint32_t addr = smu + FA_QS + row * QROWB + kk * 32 + ((lane >> 4) << 4);
        ldm_x4(addr, qf[kk][0], qf[kk][1], qf[kk][2], qf[kk][3]);
    }

    float O[8][4];
    #pragma unroll
    for (int i = 0; i < 8; i++)
        #pragma unroll
        for (int j = 0; j < 4; j++) O[i][j] = 0.f;
    float m0s = -1e30f, m1s = -1e30f, l0 = 0.f, l1 = 0.f;

    for (int c = 0; c < 64; c++){
        // wait -> barrier -> issue -> read (single sync per chunk, race-free):
        //  * CP_WAIT retires this thread's group for chunk c
        //  * barrier makes ALL threads' chunk-c copies visible AND separates last
        //    iteration's reads of stage (c+2)%3 from this iteration's overwrite
        if (c < 63) CP_WAIT(1);   // pending {kv_c, kv_c+1} -> kv_c complete
        else        CP_WAIT(0);
        __syncthreads();
        if (c + 2 < 64){
            fa_load_kv(kW, vT, kbase, vbase, c + 2, smu, (c + 2) % 3, tid);
            CP_COMMIT();
        }

        uint32_t ks = smu + FA_KV + (c % 3) * 18432;
        uint32_t vs = ks + 9216;

        float S[8][4];
        #pragma unroll
        for (int i = 0; i < 8; i++)
            #pragma unroll
            for (int j = 0; j < 4; j++) S[i][j] = 0.f;
        #pragma unroll
        for (int kk = 0; kk < 4; kk++){
            uint32_t bfr[4][4];
            #pragma unroll
            for (int np = 0; np < 4; np++){
                int row = np * 16 + ((lane & 7) | ((lane >> 4) << 3));
                uint32_t addr = ks + row * KROWB + kk * 32 + (((lane >> 3) & 1) << 4);
                ldm_x4(addr, bfr[np][0], bfr[np][1], bfr[np][2], bfr[np][3]);
            }
            #pragma unroll
            for (int nt = 0; nt < 8; nt++)
                mma16816(S[nt], qf[kk], &bfr[nt >> 1][(nt & 1) * 2]);
        }

        // S holds logits * log2(e) -> base-2 online softmax (exactly equivalent)
        float mx0 = -1e30f, mx1 = -1e30f;
        #pragma unroll
        for (int nt = 0; nt < 8; nt++){
            mx0 = fmaxf(mx0, fmaxf(S[nt][0], S[nt][1]));
            mx1 = fmaxf(mx1, fmaxf(S[nt][2], S[nt][3]));
        }
        mx0 = fmaxf(mx0, __shfl_xor_sync(0xffffffffu, mx0, 1));
        mx0 = fmaxf(mx0, __shfl_xor_sync(0xffffffffu, mx0, 2));
        mx1 = fmaxf(mx1, __shfl_xor_sync(0xffffffffu, mx1, 1));
        mx1 = fmaxf(mx1, __shfl_xor_sync(0xffffffffu, mx1, 2));
        float nm0 = fmaxf(m0s, mx0), nm1 = fmaxf(m1s, mx1);
        float sc0 = fexp2(m0s - nm0), sc1 = fexp2(m1s - nm1);
        float sum0 = 0.f, sum1 = 0.f;
        #pragma unroll
        for (int nt = 0; nt < 8; nt++){
            S[nt][0] = fexp2(S[nt][0] - nm0); sum0 += S[nt][0];
            S[nt][1] = fexp2(S[nt][1] - nm0); sum0 += S[nt][1];
            S[nt][2] = fexp2(S[nt][2] - nm1); sum1 += S[nt][2];
            S[nt][3] = fexp2(S[nt][3] - nm1); sum1 += S[nt][3];
        }
        sum0 += __shfl_xor_sync(0xffffffffu, sum0, 1);
        sum0 += __shfl_xor_sync(0xffffffffu, sum0, 2);
        sum1 += __shfl_xor_sync(0xffffffffu, sum1, 1);
        sum1 += __shfl_xor_sync(0xffffffffu, sum1, 2);
        l0 = l0 * sc0 + sum0; l1 = l1 * sc1 + sum1;
        m0s = nm0; m1s = nm1;
        #pragma unroll
        for (int nt = 0; nt < 8; nt++){
            O[nt][0] *= sc0; O[nt][1] *= sc0;
            O[nt][2] *= sc1; O[nt][3] *= sc1;
        }

        #pragma unroll
        for (int kc = 0; kc < 4; kc++){
            uint32_t ph[4];
            int ta = 2 * kc, tb = 2 * kc + 1;
            ph[0] = packh(S[ta][0], S[ta][1]);
            ph[1] = packh(S[ta][2], S[ta][3]);
            ph[2] = packh(S[tb][0], S[tb][1]);
            ph[3] = packh(S[tb][2], S[tb][3]);
            uint32_t vf[4][4];
            #pragma unroll
            for (int np = 0; np < 4; np++){
                int row = np * 16 + ((lane & 7) | ((lane >> 4) << 3));
                uint32_t col = kc * 32 + (((lane >> 3) & 1) << 4);
                ldm_x4(vs + row * VROWB + col, vf[np][0], vf[np][1], vf[np][2], vf[np][3]);
            }
            #pragma unroll
            for (int nt = 0; nt < 8; nt++)
                mma16816(O[nt], ph, &vf[nt >> 1][(nt & 1) * 2]);
        }
    }

    // ---- write O as fp16 ----
    float inv0 = 1.0f / l0, inv1 = 1.0f / l1;
    int r0 = w * 16 + (lane >> 2);
    int col = (lane & 3) * 2;
    long long tok0 = (long long)b * 4096 + m0 + r0;
    #pragma unroll
    for (int nt = 0; nt < 8; nt++){
        int d = nt * 8 + col;
        __half2 v0 = __floats2half2_rn(O[nt][0] * inv0, O[nt][1] * inv0);
        __half2 v1 = __floats2half2_rn(O[nt][2] * inv1, O[nt][3] * inv1);
        *(__half2*)(oW + tok0 * 512 + h * 64 + d)       = v0;
        *(__half2*)(oW + (tok0 + 8) * 512 + h * 64 + d) = v1;
    }
}

// ============================ LayerNorm -> fp16 (2 rows/CTA, float4) ============================
__global__ void ln_half(const float* __restrict__ x, const float* __restrict__ g,
                        const float* __restrict__ beta, __half* __restrict__ y){
    int tid = threadIdx.x;
    long long row = (long long)blockIdx.x * 2 + (tid >> 7);
    int li = tid & 127;
    const float4* xr = (const float4*)(x + row * DIMC);
    float4 a = xr[li];
    float s  = a.x + a.y + a.z + a.w;
    float ss = a.x*a.x + a.y*a.y + a.z*a.z + a.w*a.w;
    #pragma unroll
    for (int o = 16; o > 0; o >>= 1){
        s  += __shfl_xor_sync(0xffffffffu, s,  o);
        ss += __shfl_xor_sync(0xffffffffu, ss, o);
    }
    __shared__ float s1[8], s2[8];
    int wr = tid >> 5;                      // warps 0-3 row A, 4-7 row B
    if ((tid & 31) == 0){ s1[wr] = s; s2[wr] = ss; }
    __syncthreads();
    int base = (tid >> 7) * 4;
    float tot  = s1[base] + s1[base+1] + s1[base+2] + s1[base+3];
    float tot2 = s2[base] + s2[base+1] + s2[base+2] + s2[base+3];
    float mu  = tot * (1.0f / DIMC);
    float var = tot2 * (1.0f / DIMC) - mu * mu;
    float rsv = rsqrtf(var + 1e-5f);
    float4 gg = ((const float4*)g)[li];
    float4 bb = ((const float4*)beta)[li];
    __half2 h0 = __floats2half2_rn((a.x - mu) * rsv * gg.x + bb.x,
                                   (a.y - mu) * rsv * gg.y + bb.y);
    __half2 h1 = __floats2half2_rn((a.z - mu) * rsv * gg.z + bb.z,
                                   (a.w - mu) * rsv * gg.w + bb.w);
    __half2* yr = (__half2*)(y + row * DIMC);
    yr[li * 2]     = h0;
    yr[li * 2 + 1] = h1;
}

// ============================ merged weight transpose -> fp16 [N][K] ============================
// Segments (32x32 tiles): qkv 768 | pe2 256 | proj 256 | mlp1 1024 | mlp2 1024 = 3328
__global__ void thalf_all(const float* __restrict__ W0, const float* __restrict__ W1,
                          const float* __restrict__ W2, const float* __restrict__ W3,
                          const float* __restrict__ W4,
                          __half* __restrict__ O0, __half* __restrict__ O1,
                          __half* __restrict__ O2, __half* __restrict__ O3,
                          __half* __restrict__ O4){
    __shared__ float tile[32][33];
    int t = blockIdx.x;
    const float* W; __half* O; int K, N, base;
    if      (t <  768){ W = W0; O = O0; K = 512;  N = 1536; base = 0;    }
    else if (t < 1024){ W = W1; O = O1; K = 512;  N = 512;  base = 768;  }
    else if (t < 1280){ W = W2; O = O2; K = 512;  N = 512;  base = 1024; }
    else if (t < 2304){ W = W3; O = O3; K = 512;  N = 2048; base = 1280; }
    else              { W = W4; O = O4; K = 2048; N = 512;  base = 2304; }
    int lt = t - base;
    int nx = N >> 5;
    int k0 = (lt / nx) * 32, n0 = (lt % nx) * 32;
    int tx = threadIdx.x, ty = threadIdx.y;
    #pragma unroll
    for (int j = 0; j < 4; j++)
        tile[ty + j * 8][tx] = W[(long long)(k0 + ty + j * 8) * N + n0 + tx];
    __syncthreads();
    #pragma unroll
    for (int j = 0; j < 4; j++){
        int n = n0 + ty + j * 8;
        O[(long long)n * K + k0 + tx] = __float2half(tile[tx][ty + j * 8]);
    }
}

// ============================ PE layer 1 -> fp16 ============================
__global__ void pe1_half(const float* __restrict__ pos, const float* __restrict__ w1,
                         const float* __restrict__ b1, __half* __restrict__ out){
    long long idx = (long long)blockIdx.x * 256 + threadIdx.x;   // 8192*512
    int m = (int)(idx >> 9), c = (int)(idx & 511);
    float p0 = pos[m * 3], p1 = pos[m * 3 + 1], p2 = pos[m * 3 + 2];
    float v = gelu_f(p0 * w1[c] + p1 * w1[512 + c] + p2 * w1[1024 + c] + b1[c]);
    out[idx] = __float2half(v);
}

// ============================ host ============================
extern "C" void kernel_launch(void* const* d_in, const int* in_sizes, int n_in,
                              void* d_out, int out_size){
    const float* x      = (const float*)d_in[0];
    const float* pos    = (const float*)d_in[1];
    const float* qkv_w  = (const float*)d_in[2];
    const float* qkv_b  = (const float*)d_in[3];
    const float* proj_w = (const float*)d_in[4];
    const float* proj_b = (const float*)d_in[5];
    const float* pe_w1  = (const float*)d_in[6];
    const float* pe_b1  = (const float*)d_in[7];
    const float* pe_w2  = (const float*)d_in[8];
    const float* pe_b2  = (const float*)d_in[9];
    const float* mlp_w1 = (const float*)d_in[10];
    const float* mlp_b1 = (const float*)d_in[11];
    const float* mlp_w2 = (const float*)d_in[12];
    const float* mlp_b2 = (const float*)d_in[13];
    const float* n1_g   = (const float*)d_in[14];
    const float* n1_b   = (const float*)d_in[15];
    const float* n2_g   = (const float*)d_in[16];
    const float* n2_b   = (const float*)d_in[17];
    float* out = (float*)d_out;

    __half *hW, *peH, *qA, *kW, *vT, *oW, *m1W;
    __half *qkvB, *pe2B, *projB, *mlp1B, *mlp2B;
    float *x2f;
    cudaGetSymbolAddress((void**)&hW,   g_hW);
    cudaGetSymbolAddress((void**)&peH,  g_peH);
    cudaGetSymbolAddress((void**)&qA,   g_qA);
    cudaGetSymbolAddress((void**)&kW,   g_kW);
    cudaGetSymbolAddress((void**)&vT,   g_vT);
    cudaGetSymbolAddress((void**)&oW,   g_oW);
    cudaGetSymbolAddress((void**)&x2f,  g_x2f);
    cudaGetSymbolAddress((void**)&m1W,  g_m1W);
    cudaGetSymbolAddress((void**)&qkvB, g_qkvB);
    cudaGetSymbolAddress((void**)&pe2B, g_pe2B);
    cudaGetSymbolAddress((void**)&projB,g_projB);
    cudaGetSymbolAddress((void**)&mlp1B,g_mlp1B);
    cudaGetSymbolAddress((void**)&mlp2B,g_mlp2B);

    __half* peW = m1W;   // disjoint lifetime

    cudaFuncSetAttribute(mmagemm,    cudaFuncAttributeMaxDynamicSharedMemorySize, DYN_SMEM);
    cudaFuncSetAttribute(qkv_gemm,   cudaFuncAttributeMaxDynamicSharedMemorySize, DYN_SMEM);
    cudaFuncSetAttribute(flash_attn, cudaFuncAttributeMaxDynamicSharedMemorySize, FA_SMEM);

    dim3 tsb(32, 8);

    // all weight transposes in one launch
    thalf_all<<<3328, tsb>>>(qkv_w, pe_w2, proj_w, mlp_w1, mlp_w2,
                             qkvB, pe2B, projB, mlp1B, mlp2B);

    // 1. peW = fp16(gelu(pos @ pe_w1 + pe_b1)); peH = fp16(peW @ pe2B^T + pe_b2)
    pe1_half<<<(NTOK*DIMC)/256, 256>>>(pos, pe_w1, pe_b1, peW);
    mmagemm<<<dim3(4, 64, 1), 256, DYN_SMEM>>>(
        peW, pe2B, pe_b2, nullptr, nullptr, peH,
        512, 512, 512, 512, 0);

    // 2. hW = fp16(LN1(x))
    ln_half<<<NTOK/2, 256>>>(x, n1_g, n1_b, hW);

    // 3. qkv GEMM with fused operand construction
    qkv_gemm<<<dim3(12, 64, 1), 256, DYN_SMEM>>>(
        hW, qkvB, qkv_b, peH, qA, kW, vT);

    // 4. fused flash attention -> oW (fp16)
    flash_attn<<<dim3(32, 16), 256, FA_SMEM>>>(qA, kW, vT, oW);

    // 5. x2 = x + oW @ projB^T + proj_b
    mmagemm<<<dim3(4, 64, 1), 256, DYN_SMEM>>>(
        oW, projB, proj_b, x, x2f, nullptr,
        512, 512, 512, 512, 2);

    // 6. hW = fp16(LN2(x2))
    ln_half<<<NTOK/2, 256>>>(x2f, n2_g, n2_b, hW);

    // 7. m1W = fp16(gelu(hW @ mlp1B^T + mlp_b1))
    mmagemm<<<dim3(16, 64, 1), 256, DYN_SMEM>>>(
        hW, mlp1B, mlp_b1, nullptr, nullptr, m1W,
        512, 512, 512, 2048, 1);

    // 8. out = x2 + m1W @ mlp2B^T + mlp_b2
    mmagemm<<<dim3(4, 64, 1), 256, DYN_SMEM>>>(
        m1W, mlp2B, mlp_b2, x2f, out, nullptr,
        2048, 2048, 2048, 512, 2);
}